// round 2
// baseline (speedup 1.0000x reference)
#include <cuda_runtime.h>
#include <math.h>

#define TSEQ 2048
#define HID  4096
#define NH   32
#define NKV  8
#define DH   128
#define GRP  (NH / NKV)

// Scratch (allocation-free rule: __device__ globals)
__device__ float g_q[(size_t)TSEQ * NH * DH];     // roped Q, [T, NH*DH]
__device__ float g_attn[(size_t)TSEQ * NH * DH];  // attention out, [T, NH*DH]

// ---------------------------------------------------------------------------
// SGEMM: C[M,N] = A[M,K] @ B[K,N] (+ bias). Tiles 128x128x16, 8x8 per thread.
// M,N multiples of 128; K multiple of 16.
// ---------------------------------------------------------------------------
__global__ __launch_bounds__(256) void sgemm128(
    const float* __restrict__ A, const float* __restrict__ B,
    const float* __restrict__ bias, float* __restrict__ C,
    int M, int N, int K)
{
    __shared__ float As[16][128];   // transposed: As[k][m]
    __shared__ float Bs[16][128];

    const int bm = blockIdx.y << 7;
    const int bn = blockIdx.x << 7;
    const int tid = threadIdx.x;
    const int tx = tid & 15, ty = tid >> 4;

    float acc[8][8];
    #pragma unroll
    for (int i = 0; i < 8; i++)
        #pragma unroll
        for (int j = 0; j < 8; j++) acc[i][j] = 0.f;

    // A loader: each thread loads 2x float4 -> covers 128 rows x 16 cols
    const int ar = tid >> 1;            // 0..127
    const int ac = (tid & 1) << 2;      // 0 or 4 (second half at +8)
    // B loader: each thread loads 2x float4 -> 16 rows x 128 cols
    const int br = tid >> 5;            // 0..7 (second half at +8)
    const int bc = (tid & 31) << 2;     // 0..124

    const float* Ap = A + (size_t)(bm + ar) * K + ac;
    const float* Bp = B + (size_t)br * N + bn + bc;

    for (int k0 = 0; k0 < K; k0 += 16) {
        float4 av0 = *(const float4*)Ap;
        float4 av1 = *(const float4*)(Ap + 8);
        float4 bv0 = *(const float4*)Bp;
        float4 bv1 = *(const float4*)(Bp + (size_t)8 * N);
        Ap += 16;
        Bp += (size_t)16 * N;

        As[ac + 0][ar] = av0.x;
        As[ac + 1][ar] = av0.y;
        As[ac + 2][ar] = av0.z;
        As[ac + 3][ar] = av0.w;
        As[ac + 8][ar] = av1.x;
        As[ac + 9][ar] = av1.y;
        As[ac + 10][ar] = av1.z;
        As[ac + 11][ar] = av1.w;
        *(float4*)&Bs[br][bc]     = bv0;
        *(float4*)&Bs[br + 8][bc] = bv1;
        __syncthreads();

        #pragma unroll
        for (int kk = 0; kk < 16; kk++) {
            float a[8], b[8];
            *(float4*)&a[0] = *(const float4*)&As[kk][ty * 8];
            *(float4*)&a[4] = *(const float4*)&As[kk][ty * 8 + 4];
            *(float4*)&b[0] = *(const float4*)&Bs[kk][tx * 8];
            *(float4*)&b[4] = *(const float4*)&Bs[kk][tx * 8 + 4];
            #pragma unroll
            for (int i = 0; i < 8; i++)
                #pragma unroll
                for (int j = 0; j < 8; j++)
                    acc[i][j] = fmaf(a[i], b[j], acc[i][j]);
        }
        __syncthreads();
    }

    #pragma unroll
    for (int i = 0; i < 8; i++) {
        const int row = bm + ty * 8 + i;
        float* Cp = C + (size_t)row * N + bn + tx * 8;
        float vals[8];
        #pragma unroll
        for (int j = 0; j < 8; j++) vals[j] = acc[i][j];
        if (bias != nullptr) {
            #pragma unroll
            for (int j = 0; j < 8; j++) vals[j] += bias[bn + tx * 8 + j];
        }
        float4 c0 = make_float4(vals[0], vals[1], vals[2], vals[3]);
        float4 c1 = make_float4(vals[4], vals[5], vals[6], vals[7]);
        *(float4*)Cp       = c0;
        *(float4*)(Cp + 4) = c1;
    }
}

// ---------------------------------------------------------------------------
// RoPE in-place: x is [T, nheads*DH]; pairs (d, d+64) per head.
// Replicates the fp32 reference math: inv = base^(-d/64), f = pos*inv.
// ---------------------------------------------------------------------------
__global__ void rope_kernel(const int* __restrict__ positions,
                            float* __restrict__ x, int nheads)
{
    int i = blockIdx.x * blockDim.x + threadIdx.x;
    int total = TSEQ * nheads * 64;
    if (i >= total) return;
    int d = i & 63;
    int rest = i >> 6;
    int hh = rest % nheads;
    int t  = rest / nheads;

    float pos = (float)positions[t];
    float inv_freq = powf(1.0e6f, -(float)d * (1.0f / 64.0f));
    float f = pos * inv_freq;
    float s, c;
    sincosf(f, &s, &c);

    float* row = x + (size_t)t * nheads * DH + (size_t)hh * DH;
    float x1 = row[d];
    float x2 = row[d + 64];
    row[d]      = x1 * c - x2 * s;
    row[d + 64] = x2 * c + x1 * s;
}

// ---------------------------------------------------------------------------
// Flash-style causal attention (fp32). Grid: (NH, T/64). 256 threads.
// q: [T, NH*DH] (roped). kbase/vbase: [T, NKV*DH]. o: [T, NH*DH].
// ---------------------------------------------------------------------------
__global__ __launch_bounds__(256) void attn_kernel(
    const float* __restrict__ q, const float* __restrict__ kbase,
    const float* __restrict__ vbase, float* __restrict__ o)
{
    extern __shared__ float sm[];
    float* Qs = sm;                 // [64][132]
    float* Ks = Qs + 64 * 132;      // [64][132]
    float* Vs = Ks + 64 * 132;      // [64][132]
    float* Ps = Vs + 64 * 132;      // [64][65]

    const int h  = blockIdx.x;
    const int m0 = blockIdx.y << 6;
    const int kvh = h / GRP;
    const float* K = kbase + (size_t)kvh * DH;   // row stride NKV*DH
    const float* V = vbase + (size_t)kvh * DH;

    const int tid = threadIdx.x;
    const int tx = tid & 15, ty = tid >> 4;
    const float scale = 0.08838834764831843f;   // 1/sqrt(128)

    // Load Q tile (64 x 128)
    for (int i = tid; i < 64 * 32; i += 256) {
        int r = i >> 5, c4 = (i & 31) << 2;
        *(float4*)&Qs[r * 132 + c4] =
            *(const float4*)&q[(size_t)(m0 + r) * (NH * DH) + (size_t)h * DH + c4];
    }

    float acc[4][8];
    float m_run[4], l_run[4];
    #pragma unroll
    for (int i = 0; i < 4; i++) {
        m_run[i] = -1e30f;
        l_run[i] = 0.f;
        #pragma unroll
        for (int kk = 0; kk < 8; kk++) acc[i][kk] = 0.f;
    }

    const int nblocks = (m0 >> 6) + 1;
    for (int nb = 0; nb < nblocks; nb++) {
        const int n0 = nb << 6;
        __syncthreads();
        // Load K,V tiles (64 x 128 each)
        for (int i = tid; i < 64 * 32; i += 256) {
            int r = i >> 5, c4 = (i & 31) << 2;
            size_t g = (size_t)(n0 + r) * (NKV * DH) + c4;
            *(float4*)&Ks[r * 132 + c4] = *(const float4*)&K[g];
            *(float4*)&Vs[r * 132 + c4] = *(const float4*)&V[g];
        }
        __syncthreads();

        // S = Q K^T  (4x4 per thread: rows ty*4.., cols tx*4..)
        float s[4][4];
        #pragma unroll
        for (int i = 0; i < 4; i++)
            #pragma unroll
            for (int j = 0; j < 4; j++) s[i][j] = 0.f;

        for (int d = 0; d < DH; d += 4) {
            float4 qa[4], kb[4];
            #pragma unroll
            for (int i = 0; i < 4; i++)
                qa[i] = *(const float4*)&Qs[(ty * 4 + i) * 132 + d];
            #pragma unroll
            for (int j = 0; j < 4; j++)
                kb[j] = *(const float4*)&Ks[(tx * 4 + j) * 132 + d];
            #pragma unroll
            for (int i = 0; i < 4; i++)
                #pragma unroll
                for (int j = 0; j < 4; j++) {
                    s[i][j] = fmaf(qa[i].x, kb[j].x, s[i][j]);
                    s[i][j] = fmaf(qa[i].y, kb[j].y, s[i][j]);
                    s[i][j] = fmaf(qa[i].z, kb[j].z, s[i][j]);
                    s[i][j] = fmaf(qa[i].w, kb[j].w, s[i][j]);
                }
        }

        const bool diag = (nb == nblocks - 1);
        // Online softmax (row reductions across tx via 16-lane shfl groups)
        #pragma unroll
        for (int i = 0; i < 4; i++) {
            const int gr = m0 + ty * 4 + i;
            float mx = -1e30f;
            #pragma unroll
            for (int j = 0; j < 4; j++) {
                float val = s[i][j] * scale;
                if (diag && (n0 + tx * 4 + j) > gr) val = -1e30f;
                s[i][j] = val;
                mx = fmaxf(mx, val);
            }
            #pragma unroll
            for (int off = 8; off > 0; off >>= 1)
                mx = fmaxf(mx, __shfl_xor_sync(0xffffffffu, mx, off));
            float mnew = fmaxf(m_run[i], mx);
            float cf = __expf(m_run[i] - mnew);
            m_run[i] = mnew;
            float su = 0.f;
            #pragma unroll
            for (int j = 0; j < 4; j++) {
                float p = __expf(s[i][j] - mnew);
                Ps[(ty * 4 + i) * 65 + tx * 4 + j] = p;
                su += p;
            }
            #pragma unroll
            for (int off = 8; off > 0; off >>= 1)
                su += __shfl_xor_sync(0xffffffffu, su, off);
            l_run[i] = l_run[i] * cf + su;
            #pragma unroll
            for (int kk = 0; kk < 8; kk++) acc[i][kk] *= cf;
        }
        __syncthreads();

        // O += P V   (o cols tx*8..+7)
        #pragma unroll 2
        for (int c = 0; c < 64; c++) {
            float vv[8];
            *(float4*)&vv[0] = *(const float4*)&Vs[c * 132 + tx * 8];
            *(float4*)&vv[4] = *(const float4*)&Vs[c * 132 + tx * 8 + 4];
            #pragma unroll
            for (int i = 0; i < 4; i++) {
                float p = Ps[(ty * 4 + i) * 65 + c];
                #pragma unroll
                for (int kk = 0; kk < 8; kk++)
                    acc[i][kk] = fmaf(p, vv[kk], acc[i][kk]);
            }
        }
    }

    // Epilogue: normalize and write [T, NH*DH]
    #pragma unroll
    for (int i = 0; i < 4; i++) {
        float inv = 1.0f / l_run[i];
        int row = m0 + ty * 4 + i;
        float4 o0 = make_float4(acc[i][0] * inv, acc[i][1] * inv,
                                acc[i][2] * inv, acc[i][3] * inv);
        float4 o1 = make_float4(acc[i][4] * inv, acc[i][5] * inv,
                                acc[i][6] * inv, acc[i][7] * inv);
        float* op = o + (size_t)row * (NH * DH) + (size_t)h * DH + tx * 8;
        *(float4*)op       = o0;
        *(float4*)(op + 4) = o1;
    }
}

// ---------------------------------------------------------------------------
extern "C" void kernel_launch(void* const* d_in, const int* in_sizes, int n_in,
                              void* d_out, int out_size)
{
    const int*   positions = (const int*)d_in[0];
    const float* hs = (const float*)d_in[1];
    const float* Wq = (const float*)d_in[2];
    const float* bq = (const float*)d_in[3];
    const float* Wk = (const float*)d_in[4];
    const float* bk = (const float*)d_in[5];
    const float* Wv = (const float*)d_in[6];
    const float* bv = (const float*)d_in[7];
    const float* Wo = (const float*)d_in[8];

    float* out  = (float*)d_out;                        // [T, HID]
    float* kout = out + (size_t)TSEQ * HID;             // kv_fused[0]: [T, NKV, DH]
    float* vout = kout + (size_t)TSEQ * NKV * DH;       // kv_fused[1]

    float *qbuf = nullptr, *abuf = nullptr;
    cudaGetSymbolAddress((void**)&qbuf, g_q);
    cudaGetSymbolAddress((void**)&abuf, g_attn);

    dim3 blk(256);
    // Projections
    sgemm128<<<dim3(NH * DH / 128, TSEQ / 128), blk>>>(hs, Wq, bq, qbuf, TSEQ, NH * DH, HID);
    sgemm128<<<dim3(NKV * DH / 128, TSEQ / 128), blk>>>(hs, Wk, bk, kout, TSEQ, NKV * DH, HID);
    sgemm128<<<dim3(NKV * DH / 128, TSEQ / 128), blk>>>(hs, Wv, bv, vout, TSEQ, NKV * DH, HID);

    // RoPE (in-place on Q scratch and K output region)
    int tot_q = TSEQ * NH * 64;
    rope_kernel<<<(tot_q + 255) / 256, 256>>>(positions, qbuf, NH);
    int tot_k = TSEQ * NKV * 64;
    rope_kernel<<<(tot_k + 255) / 256, 256>>>(positions, kout, NKV);

    // Attention
    const size_t ATTN_SMEM = (size_t)(3 * 64 * 132 + 64 * 65) * sizeof(float); // 118016 B
    cudaFuncSetAttribute(attn_kernel, cudaFuncAttributeMaxDynamicSharedMemorySize,
                         (int)ATTN_SMEM);
    attn_kernel<<<dim3(NH, TSEQ / 64), blk, ATTN_SMEM>>>(qbuf, kout, vout, abuf);

    // Output projection
    sgemm128<<<dim3(HID / 128, TSEQ / 128), blk>>>(abuf, Wo, nullptr, out, TSEQ, HID, NH * DH);
}

// round 4
// speedup vs baseline: 1.7635x; 1.7635x over previous
#include <cuda_runtime.h>
#include <cuda_bf16.h>
#include <math.h>
#include <stdint.h>

#define TSEQ 2048
#define HID  4096
#define NH   32
#define NKV  8
#define DH   128
#define GRP  (NH / NKV)

// Scratch (allocation-free rule: __device__ globals)
__device__ float g_q[(size_t)TSEQ * NH * DH];     // roped Q, [T, NH*DH]
__device__ float g_attn[(size_t)TSEQ * NH * DH];  // attention out, [T, NH*DH]

// ---------------------------------------------------------------------------
// helpers
// ---------------------------------------------------------------------------
__device__ __forceinline__ uint32_t smem_u32(const void* p) {
    uint32_t a;
    asm("{ .reg .u64 t; cvta.to.shared.u64 t, %1; cvt.u32.u64 %0, t; }"
        : "=r"(a) : "l"(p));
    return a;
}
__device__ __forceinline__ uint32_t cvt_bf16x2(float hi, float lo) {
    uint32_t r;
    asm("cvt.rn.bf16x2.f32 %0, %1, %2;" : "=r"(r) : "f"(hi), "f"(lo));
    return r;
}
__device__ __forceinline__ void ldsm4(uint32_t (&r)[4], uint32_t a) {
    asm volatile("ldmatrix.sync.aligned.m8n8.x4.shared.b16 {%0,%1,%2,%3}, [%4];"
        : "=r"(r[0]), "=r"(r[1]), "=r"(r[2]), "=r"(r[3]) : "r"(a));
}
__device__ __forceinline__ void ldsm4t(uint32_t (&r)[4], uint32_t a) {
    asm volatile("ldmatrix.sync.aligned.m8n8.x4.trans.shared.b16 {%0,%1,%2,%3}, [%4];"
        : "=r"(r[0]), "=r"(r[1]), "=r"(r[2]), "=r"(r[3]) : "r"(a));
}
__device__ __forceinline__ void mma_bf16(float (&c)[4], const uint32_t (&a)[4],
                                         uint32_t b0, uint32_t b1) {
    asm volatile("mma.sync.aligned.m16n8k16.row.col.f32.bf16.bf16.f32 "
        "{%0,%1,%2,%3}, {%4,%5,%6,%7}, {%8,%9}, {%0,%1,%2,%3};"
        : "+f"(c[0]), "+f"(c[1]), "+f"(c[2]), "+f"(c[3])
        : "r"(a[0]), "r"(a[1]), "r"(a[2]), "r"(a[3]), "r"(b0), "r"(b1));
}

// ---------------------------------------------------------------------------
// Tensor-core GEMM via mma.sync (bf16 split hi/lo, 3 products, fp32 accum).
// C[M,N] = A[M,K] @ B[K,N] (+bias). CTA tile 128x128, K-chunk 32,
// double-buffered smem, register prefetch. 256 threads (8 warps 4Mx2N).
// Requires K % 32 == 0, M,N % 128 == 0.
// ---------------------------------------------------------------------------
// smem layout (bytes):
//   Ahi[2]: [128][40] bf16 (row 80B: 32 data + 8 pad)  -> 10240 each
//   Alo[2]: same
//   Bhi[2]: [32][136] bf16 (row 272B: 128 data + 8 pad) -> 8704 each
//   Blo[2]: same
#define A_TILE 10240
#define B_TILE 8704
#define OFF_AHI(b) ((uint32_t)(b) * A_TILE)
#define OFF_ALO(b) (2u * A_TILE + (uint32_t)(b) * A_TILE)
#define OFF_BHI(b) (4u * A_TILE + (uint32_t)(b) * B_TILE)
#define OFF_BLO(b) (4u * A_TILE + 2u * B_TILE + (uint32_t)(b) * B_TILE)
#define GSM_TOTAL (4 * A_TILE + 4 * B_TILE)   // 75776 bytes

__global__ __launch_bounds__(256, 1) void tgemm(
    const float* __restrict__ A, const float* __restrict__ B,
    const float* __restrict__ bias, float* __restrict__ C,
    int M, int N, int K)
{
    extern __shared__ char smraw[];
    const uint32_t sbase = smem_u32(smraw);

    const int tid  = threadIdx.x;
    const int wid  = tid >> 5;
    const int lane = tid & 31;
    const int bm = blockIdx.y << 7;
    const int bn = blockIdx.x << 7;
    const int wm = (wid >> 1) << 5;   // 0/32/64/96
    const int wn = (wid & 1) << 6;    // 0/64

    // loader indices (4 float4 per thread for A and for B)
    int arow[4], acol[4], brow[4], bcol[4];
    #pragma unroll
    for (int i = 0; i < 4; i++) {
        int idx = tid + i * 256;          // 0..1023
        arow[i] = idx >> 3;               // 128 rows, 8 float4/row
        acol[i] = (idx & 7) << 2;         // 0..28
        brow[i] = idx >> 5;               // 32 rows, 32 float4/row
        bcol[i] = (idx & 31) << 2;        // 0..124
    }

    float acc[2][8][4];
    #pragma unroll
    for (int mi = 0; mi < 2; mi++)
        #pragma unroll
        for (int j = 0; j < 8; j++)
            #pragma unroll
            for (int q = 0; q < 4; q++) acc[mi][j][q] = 0.f;

    float4 pa[4], pb[4];
    const int NC = K >> 5;

    // prefetch chunk 0
    #pragma unroll
    for (int i = 0; i < 4; i++) {
        pa[i] = *(const float4*)(A + (size_t)(bm + arow[i]) * K + acol[i]);
        pb[i] = *(const float4*)(B + (size_t)brow[i] * N + bn + bcol[i]);
    }
    // convert + store chunk 0 -> buf 0
    {
        const int b = 0;
        #pragma unroll
        for (int i = 0; i < 4; i++) {
            float4 v = pa[i];
            uint32_t h0 = cvt_bf16x2(v.y, v.x);
            uint32_t h1 = cvt_bf16x2(v.w, v.z);
            float r0 = v.x - __uint_as_float(h0 << 16);
            float r1 = v.y - __uint_as_float(h0 & 0xFFFF0000u);
            float r2 = v.z - __uint_as_float(h1 << 16);
            float r3 = v.w - __uint_as_float(h1 & 0xFFFF0000u);
            uint32_t l0 = cvt_bf16x2(r1, r0);
            uint32_t l1 = cvt_bf16x2(r3, r2);
            uint32_t off = (uint32_t)(arow[i] * 80 + acol[i] * 2);
            *(uint2*)(smraw + OFF_AHI(b) + off) = make_uint2(h0, h1);
            *(uint2*)(smraw + OFF_ALO(b) + off) = make_uint2(l0, l1);
        }
        #pragma unroll
        for (int i = 0; i < 4; i++) {
            float4 v = pb[i];
            uint32_t h0 = cvt_bf16x2(v.y, v.x);
            uint32_t h1 = cvt_bf16x2(v.w, v.z);
            float r0 = v.x - __uint_as_float(h0 << 16);
            float r1 = v.y - __uint_as_float(h0 & 0xFFFF0000u);
            float r2 = v.z - __uint_as_float(h1 << 16);
            float r3 = v.w - __uint_as_float(h1 & 0xFFFF0000u);
            uint32_t l0 = cvt_bf16x2(r1, r0);
            uint32_t l1 = cvt_bf16x2(r3, r2);
            uint32_t off = (uint32_t)(brow[i] * 272 + bcol[i] * 2);
            *(uint2*)(smraw + OFF_BHI(b) + off) = make_uint2(h0, h1);
            *(uint2*)(smraw + OFF_BLO(b) + off) = make_uint2(l0, l1);
        }
    }
    __syncthreads();

    for (int c = 0; c < NC; c++) {
        const int b = c & 1;
        const bool more = (c + 1 < NC);
        if (more) {
            const int k0 = (c + 1) << 5;
            #pragma unroll
            for (int i = 0; i < 4; i++) {
                pa[i] = *(const float4*)(A + (size_t)(bm + arow[i]) * K + k0 + acol[i]);
                pb[i] = *(const float4*)(B + (size_t)(k0 + brow[i]) * N + bn + bcol[i]);
            }
        }

        // ---- compute chunk c from buffer b ----
        const uint32_t aH = sbase + OFF_AHI(b);
        const uint32_t aL = sbase + OFF_ALO(b);
        const uint32_t bH = sbase + OFF_BHI(b);
        const uint32_t bL = sbase + OFF_BLO(b);
        #pragma unroll
        for (int ks = 0; ks < 2; ks++) {
            uint32_t afh[2][4], afl[2][4], bfh[4][4], bfl[4][4];
            const uint32_t acolo = (uint32_t)(ks * 32 + (lane >> 4) * 16);
            #pragma unroll
            for (int mi = 0; mi < 2; mi++) {
                uint32_t ro = (uint32_t)((wm + mi * 16 + (lane & 15)) * 80) + acolo;
                ldsm4(afh[mi], aH + ro);
                ldsm4(afl[mi], aL + ro);
            }
            const uint32_t kro = (uint32_t)((ks * 16 + (lane & 15)) * 272);
            #pragma unroll
            for (int nb = 0; nb < 4; nb++) {
                uint32_t no = kro + (uint32_t)((wn + nb * 16) * 2 + (lane >> 4) * 16);
                ldsm4t(bfh[nb], bH + no);
                ldsm4t(bfl[nb], bL + no);
            }
            #pragma unroll
            for (int mi = 0; mi < 2; mi++)
                #pragma unroll
                for (int nb = 0; nb < 4; nb++)
                    #pragma unroll
                    for (int hh = 0; hh < 2; hh++) {
                        float (&cc)[4] = acc[mi][nb * 2 + hh];
                        mma_bf16(cc, afh[mi], bfh[nb][2 * hh], bfh[nb][2 * hh + 1]);
                        mma_bf16(cc, afh[mi], bfl[nb][2 * hh], bfl[nb][2 * hh + 1]);
                        mma_bf16(cc, afl[mi], bfh[nb][2 * hh], bfh[nb][2 * hh + 1]);
                    }
        }

        // ---- convert + store chunk c+1 into buffer b^1 ----
        if (more) {
            const int nb2 = b ^ 1;
            #pragma unroll
            for (int i = 0; i < 4; i++) {
                float4 v = pa[i];
                uint32_t h0 = cvt_bf16x2(v.y, v.x);
                uint32_t h1 = cvt_bf16x2(v.w, v.z);
                float r0 = v.x - __uint_as_float(h0 << 16);
                float r1 = v.y - __uint_as_float(h0 & 0xFFFF0000u);
                float r2 = v.z - __uint_as_float(h1 << 16);
                float r3 = v.w - __uint_as_float(h1 & 0xFFFF0000u);
                uint32_t l0 = cvt_bf16x2(r1, r0);
                uint32_t l1 = cvt_bf16x2(r3, r2);
                uint32_t off = (uint32_t)(arow[i] * 80 + acol[i] * 2);
                *(uint2*)(smraw + OFF_AHI(nb2) + off) = make_uint2(h0, h1);
                *(uint2*)(smraw + OFF_ALO(nb2) + off) = make_uint2(l0, l1);
            }
            #pragma unroll
            for (int i = 0; i < 4; i++) {
                float4 v = pb[i];
                uint32_t h0 = cvt_bf16x2(v.y, v.x);
                uint32_t h1 = cvt_bf16x2(v.w, v.z);
                float r0 = v.x - __uint_as_float(h0 << 16);
                float r1 = v.y - __uint_as_float(h0 & 0xFFFF0000u);
                float r2 = v.z - __uint_as_float(h1 << 16);
                float r3 = v.w - __uint_as_float(h1 & 0xFFFF0000u);
                uint32_t l0 = cvt_bf16x2(r1, r0);
                uint32_t l1 = cvt_bf16x2(r3, r2);
                uint32_t off = (uint32_t)(brow[i] * 272 + bcol[i] * 2);
                *(uint2*)(smraw + OFF_BHI(nb2) + off) = make_uint2(h0, h1);
                *(uint2*)(smraw + OFF_BLO(nb2) + off) = make_uint2(l0, l1);
            }
        }
        __syncthreads();
    }

    // ---- epilogue ----
    const int r0 = lane >> 2;
    const int c0 = (lane & 3) << 1;
    #pragma unroll
    for (int mi = 0; mi < 2; mi++) {
        #pragma unroll
        for (int j = 0; j < 8; j++) {
            const int col = bn + wn + j * 8 + c0;
            float bias0 = 0.f, bias1 = 0.f;
            if (bias != nullptr) { bias0 = bias[col]; bias1 = bias[col + 1]; }
            const int row_a = bm + wm + mi * 16 + r0;
            const int row_b = row_a + 8;
            float* Ca = C + (size_t)row_a * N + col;
            float* Cb = C + (size_t)row_b * N + col;
            Ca[0] = acc[mi][j][0] + bias0;
            Ca[1] = acc[mi][j][1] + bias1;
            Cb[0] = acc[mi][j][2] + bias0;
            Cb[1] = acc[mi][j][3] + bias1;
        }
    }
}

// ---------------------------------------------------------------------------
// RoPE in-place: x is [T, nheads*DH]; pairs (d, d+64) per head.
// ---------------------------------------------------------------------------
__global__ void rope_kernel(const int* __restrict__ positions,
                            float* __restrict__ x, int nheads)
{
    int i = blockIdx.x * blockDim.x + threadIdx.x;
    int total = TSEQ * nheads * 64;
    if (i >= total) return;
    int d = i & 63;
    int rest = i >> 6;
    int hh = rest % nheads;
    int t  = rest / nheads;

    float pos = (float)positions[t];
    float inv_freq = powf(1.0e6f, -(float)d * (1.0f / 64.0f));
    float f = pos * inv_freq;
    float s, c;
    sincosf(f, &s, &c);

    float* row = x + (size_t)t * nheads * DH + (size_t)hh * DH;
    float x1 = row[d];
    float x2 = row[d + 64];
    row[d]      = x1 * c - x2 * s;
    row[d + 64] = x2 * c + x1 * s;
}

// ---------------------------------------------------------------------------
// Flash-style causal attention (fp32). Grid: (NH, T/64). 256 threads.
// ---------------------------------------------------------------------------
__global__ __launch_bounds__(256) void attn_kernel(
    const float* __restrict__ q, const float* __restrict__ kbase,
    const float* __restrict__ vbase, float* __restrict__ o)
{
    extern __shared__ float sm[];
    float* Qs = sm;                 // [64][132]
    float* Ks = Qs + 64 * 132;      // [64][132]
    float* Vs = Ks + 64 * 132;      // [64][132]
    float* Ps = Vs + 64 * 132;      // [64][65]

    const int h  = blockIdx.x;
    const int m0 = blockIdx.y << 6;
    const int kvh = h / GRP;
    const float* K = kbase + (size_t)kvh * DH;
    const float* V = vbase + (size_t)kvh * DH;

    const int tid = threadIdx.x;
    const int tx = tid & 15, ty = tid >> 4;
    const float scale = 0.08838834764831843f;

    for (int i = tid; i < 64 * 32; i += 256) {
        int r = i >> 5, c4 = (i & 31) << 2;
        *(float4*)&Qs[r * 132 + c4] =
            *(const float4*)&q[(size_t)(m0 + r) * (NH * DH) + (size_t)h * DH + c4];
    }

    float acc[4][8];
    float m_run[4], l_run[4];
    #pragma unroll
    for (int i = 0; i < 4; i++) {
        m_run[i] = -1e30f;
        l_run[i] = 0.f;
        #pragma unroll
        for (int kk = 0; kk < 8; kk++) acc[i][kk] = 0.f;
    }

    const int nblocks = (m0 >> 6) + 1;
    for (int nb = 0; nb < nblocks; nb++) {
        const int n0 = nb << 6;
        __syncthreads();
        for (int i = tid; i < 64 * 32; i += 256) {
            int r = i >> 5, c4 = (i & 31) << 2;
            size_t g = (size_t)(n0 + r) * (NKV * DH) + c4;
            *(float4*)&Ks[r * 132 + c4] = *(const float4*)&K[g];
            *(float4*)&Vs[r * 132 + c4] = *(const float4*)&V[g];
        }
        __syncthreads();

        float s[4][4];
        #pragma unroll
        for (int i = 0; i < 4; i++)
            #pragma unroll
            for (int j = 0; j < 4; j++) s[i][j] = 0.f;

        for (int d = 0; d < DH; d += 4) {
            float4 qa[4], kb[4];
            #pragma unroll
            for (int i = 0; i < 4; i++)
                qa[i] = *(const float4*)&Qs[(ty * 4 + i) * 132 + d];
            #pragma unroll
            for (int j = 0; j < 4; j++)
                kb[j] = *(const float4*)&Ks[(tx * 4 + j) * 132 + d];
            #pragma unroll
            for (int i = 0; i < 4; i++)
                #pragma unroll
                for (int j = 0; j < 4; j++) {
                    s[i][j] = fmaf(qa[i].x, kb[j].x, s[i][j]);
                    s[i][j] = fmaf(qa[i].y, kb[j].y, s[i][j]);
                    s[i][j] = fmaf(qa[i].z, kb[j].z, s[i][j]);
                    s[i][j] = fmaf(qa[i].w, kb[j].w, s[i][j]);
                }
        }

        const bool diag = (nb == nblocks - 1);
        #pragma unroll
        for (int i = 0; i < 4; i++) {
            const int gr = m0 + ty * 4 + i;
            float mx = -1e30f;
            #pragma unroll
            for (int j = 0; j < 4; j++) {
                float val = s[i][j] * scale;
                if (diag && (n0 + tx * 4 + j) > gr) val = -1e30f;
                s[i][j] = val;
                mx = fmaxf(mx, val);
            }
            #pragma unroll
            for (int off = 8; off > 0; off >>= 1)
                mx = fmaxf(mx, __shfl_xor_sync(0xffffffffu, mx, off));
            float mnew = fmaxf(m_run[i], mx);
            float cf = __expf(m_run[i] - mnew);
            m_run[i] = mnew;
            float su = 0.f;
            #pragma unroll
            for (int j = 0; j < 4; j++) {
                float p = __expf(s[i][j] - mnew);
                Ps[(ty * 4 + i) * 65 + tx * 4 + j] = p;
                su += p;
            }
            #pragma unroll
            for (int off = 8; off > 0; off >>= 1)
                su += __shfl_xor_sync(0xffffffffu, su, off);
            l_run[i] = l_run[i] * cf + su;
            #pragma unroll
            for (int kk = 0; kk < 8; kk++) acc[i][kk] *= cf;
        }
        __syncthreads();

        #pragma unroll 2
        for (int c = 0; c < 64; c++) {
            float vv[8];
            *(float4*)&vv[0] = *(const float4*)&Vs[c * 132 + tx * 8];
            *(float4*)&vv[4] = *(const float4*)&Vs[c * 132 + tx * 8 + 4];
            #pragma unroll
            for (int i = 0; i < 4; i++) {
                float p = Ps[(ty * 4 + i) * 65 + c];
                #pragma unroll
                for (int kk = 0; kk < 8; kk++)
                    acc[i][kk] = fmaf(p, vv[kk], acc[i][kk]);
            }
        }
    }

    #pragma unroll
    for (int i = 0; i < 4; i++) {
        float inv = 1.0f / l_run[i];
        int row = m0 + ty * 4 + i;
        float4 o0 = make_float4(acc[i][0] * inv, acc[i][1] * inv,
                                acc[i][2] * inv, acc[i][3] * inv);
        float4 o1 = make_float4(acc[i][4] * inv, acc[i][5] * inv,
                                acc[i][6] * inv, acc[i][7] * inv);
        float* op = o + (size_t)row * (NH * DH) + (size_t)h * DH + tx * 8;
        *(float4*)op       = o0;
        *(float4*)(op + 4) = o1;
    }
}

// ---------------------------------------------------------------------------
extern "C" void kernel_launch(void* const* d_in, const int* in_sizes, int n_in,
                              void* d_out, int out_size)
{
    const int*   positions = (const int*)d_in[0];
    const float* hs = (const float*)d_in[1];
    const float* Wq = (const float*)d_in[2];
    const float* bq = (const float*)d_in[3];
    const float* Wk = (const float*)d_in[4];
    const float* bk = (const float*)d_in[5];
    const float* Wv = (const float*)d_in[6];
    const float* bv = (const float*)d_in[7];
    const float* Wo = (const float*)d_in[8];

    float* out  = (float*)d_out;                        // [T, HID]
    float* kout = out + (size_t)TSEQ * HID;             // kv_fused[0]
    float* vout = kout + (size_t)TSEQ * NKV * DH;       // kv_fused[1]

    float *qbuf = nullptr, *abuf = nullptr;
    cudaGetSymbolAddress((void**)&qbuf, g_q);
    cudaGetSymbolAddress((void**)&abuf, g_attn);

    cudaFuncSetAttribute(tgemm, cudaFuncAttributeMaxDynamicSharedMemorySize, GSM_TOTAL);

    // Projections (mma.sync bf16 split hi/lo)
    tgemm<<<dim3(NH * DH / 128, TSEQ / 128), 256, GSM_TOTAL>>>(hs, Wq, bq, qbuf, TSEQ, NH * DH, HID);
    tgemm<<<dim3(NKV * DH / 128, TSEQ / 128), 256, GSM_TOTAL>>>(hs, Wk, bk, kout, TSEQ, NKV * DH, HID);
    tgemm<<<dim3(NKV * DH / 128, TSEQ / 128), 256, GSM_TOTAL>>>(hs, Wv, bv, vout, TSEQ, NKV * DH, HID);

    // RoPE
    int tot_q = TSEQ * NH * 64;
    rope_kernel<<<(tot_q + 255) / 256, 256>>>(positions, qbuf, NH);
    int tot_k = TSEQ * NKV * 64;
    rope_kernel<<<(tot_k + 255) / 256, 256>>>(positions, kout, NKV);

    // Attention (fp32)
    const size_t ATTN_SMEM = (size_t)(3 * 64 * 132 + 64 * 65) * sizeof(float);
    cudaFuncSetAttribute(attn_kernel, cudaFuncAttributeMaxDynamicSharedMemorySize,
                         (int)ATTN_SMEM);
    attn_kernel<<<dim3(NH, TSEQ / 64), 256, ATTN_SMEM>>>(qbuf, kout, vout, abuf);

    // Output projection
    tgemm<<<dim3(HID / 128, TSEQ / 128), 256, GSM_TOTAL>>>(abuf, Wo, nullptr, out, TSEQ, HID, NH * DH);
}

// round 5
// speedup vs baseline: 2.9283x; 1.6605x over previous
#include <cuda_runtime.h>
#include <cuda_bf16.h>
#include <math.h>
#include <stdint.h>

#define TSEQ 2048
#define HID  4096
#define NH   32
#define NKV  8
#define DH   128
#define GRP  (NH / NKV)

// ---------------------------------------------------------------------------
// Scratch (allocation-free rule: __device__ globals)
// ---------------------------------------------------------------------------
__device__ float g_q[(size_t)TSEQ * NH * DH];      // fp32 Q (pre-rope)
__device__ float g_attn[(size_t)TSEQ * NH * DH];   // fp32 attention out
// pre-split bf16 hi/lo arrays
__device__ __nv_bfloat16 g_hsh[(size_t)TSEQ * HID],      g_hsl[(size_t)TSEQ * HID];
__device__ __nv_bfloat16 g_wqh[(size_t)HID * NH * DH],   g_wql[(size_t)HID * NH * DH];
__device__ __nv_bfloat16 g_wkh[(size_t)HID * NKV * DH],  g_wkl[(size_t)HID * NKV * DH];
__device__ __nv_bfloat16 g_wvh[(size_t)HID * NKV * DH],  g_wvl[(size_t)HID * NKV * DH];
__device__ __nv_bfloat16 g_woh[(size_t)NH * DH * HID],   g_wol[(size_t)NH * DH * HID];
__device__ __nv_bfloat16 g_qh[(size_t)TSEQ * NH * DH],   g_ql[(size_t)TSEQ * NH * DH];
__device__ __nv_bfloat16 g_kh[(size_t)TSEQ * NKV * DH],  g_kl[(size_t)TSEQ * NKV * DH];
__device__ __nv_bfloat16 g_vh[(size_t)TSEQ * NKV * DH],  g_vl[(size_t)TSEQ * NKV * DH];
__device__ __nv_bfloat16 g_ah[(size_t)TSEQ * NH * DH],   g_al[(size_t)TSEQ * NH * DH];

// ---------------------------------------------------------------------------
// helpers
// ---------------------------------------------------------------------------
__device__ __forceinline__ uint32_t smem_u32(const void* p) {
    uint32_t a;
    asm("{ .reg .u64 t; cvta.to.shared.u64 t, %1; cvt.u32.u64 %0, t; }"
        : "=r"(a) : "l"(p));
    return a;
}
__device__ __forceinline__ uint32_t cvt_bf16x2(float hi, float lo) {
    uint32_t r;
    asm("cvt.rn.bf16x2.f32 %0, %1, %2;" : "=r"(r) : "f"(hi), "f"(lo));
    return r;
}
__device__ __forceinline__ void ldsm4(uint32_t (&r)[4], uint32_t a) {
    asm volatile("ldmatrix.sync.aligned.m8n8.x4.shared.b16 {%0,%1,%2,%3}, [%4];"
        : "=r"(r[0]), "=r"(r[1]), "=r"(r[2]), "=r"(r[3]) : "r"(a));
}
__device__ __forceinline__ void ldsm4t(uint32_t (&r)[4], uint32_t a) {
    asm volatile("ldmatrix.sync.aligned.m8n8.x4.trans.shared.b16 {%0,%1,%2,%3}, [%4];"
        : "=r"(r[0]), "=r"(r[1]), "=r"(r[2]), "=r"(r[3]) : "r"(a));
}
__device__ __forceinline__ void mma_bf16(float (&c)[4], const uint32_t (&a)[4],
                                         uint32_t b0, uint32_t b1) {
    asm volatile("mma.sync.aligned.m16n8k16.row.col.f32.bf16.bf16.f32 "
        "{%0,%1,%2,%3}, {%4,%5,%6,%7}, {%8,%9}, {%0,%1,%2,%3};"
        : "+f"(c[0]), "+f"(c[1]), "+f"(c[2]), "+f"(c[3])
        : "r"(a[0]), "r"(a[1]), "r"(a[2]), "r"(a[3]), "r"(b0), "r"(b1));
}
__device__ __forceinline__ void cp16(uint32_t dst, const void* src) {
    asm volatile("cp.async.cg.shared.global [%0], [%1], 16;" :: "r"(dst), "l"(src));
}
#define CP_COMMIT() asm volatile("cp.async.commit_group;" ::: "memory")
#define CP_WAIT(n)  asm volatile("cp.async.wait_group %0;" :: "n"(n) : "memory")

__device__ __forceinline__ void split_pack(float x, float y, uint32_t& hi, uint32_t& lo) {
    hi = cvt_bf16x2(y, x);
    float rx = x - __uint_as_float(hi << 16);
    float ry = y - __uint_as_float(hi & 0xFFFF0000u);
    lo = cvt_bf16x2(ry, rx);
}

// ---------------------------------------------------------------------------
// convert fp32 -> bf16 hi + bf16 lo (residual), vectorized by 4
// ---------------------------------------------------------------------------
__global__ void convert_split(const float4* __restrict__ in,
                              uint2* __restrict__ hi, uint2* __restrict__ lo, int n4)
{
    int i = blockIdx.x * blockDim.x + threadIdx.x;
    if (i >= n4) return;
    float4 v = in[i];
    uint32_t h0, l0, h1, l1;
    split_pack(v.x, v.y, h0, l0);
    split_pack(v.z, v.w, h1, l1);
    hi[i] = make_uint2(h0, h1);
    lo[i] = make_uint2(l0, l1);
}

// ---------------------------------------------------------------------------
// Tensor-core GEMM from pre-split bf16 hi/lo inputs.
// C[M,N] = A[M,K] @ B[K,N] (+bias), fp32 out. CTA 128x128, K-chunk 64,
// cp.async double-buffer. 256 threads, 8 warps (4Mx2N).
// ---------------------------------------------------------------------------
#define TG_AT 18432u            // A tile [128][144B]
#define TG_BT 17408u            // B tile [64][272B]
#define TG_BUF (2u * TG_AT + 2u * TG_BT)    // 71680
#define TG_SMEM (2u * TG_BUF)               // 143360

__global__ __launch_bounds__(256, 1) void tgemm2(
    const __nv_bfloat16* __restrict__ Ah, const __nv_bfloat16* __restrict__ Al,
    const __nv_bfloat16* __restrict__ Bh, const __nv_bfloat16* __restrict__ Bl,
    const float* __restrict__ bias, float* __restrict__ C,
    int M, int N, int K)
{
    extern __shared__ char sm[];
    const uint32_t sb = smem_u32(sm);

    const int tid  = threadIdx.x;
    const int wid  = tid >> 5;
    const int lane = tid & 31;
    const int bm = blockIdx.y << 7;
    const int bn = blockIdx.x << 7;
    const int wm = (wid >> 1) << 5;
    const int wn = (wid & 1) << 6;

    auto issue = [&](int k0, int buf) {
        const uint32_t base = sb + (uint32_t)buf * TG_BUF;
        #pragma unroll
        for (int i = 0; i < 4; i++) {
            int idx = tid + i * 256;          // 0..1023
            int ar = idx >> 3, ac = idx & 7;  // A: 128 rows x 8 chunks
            const size_t aoff = (size_t)(bm + ar) * K + k0 + ac * 8;
            cp16(base + (uint32_t)(ar * 144 + ac * 16), Ah + aoff);
            cp16(base + TG_AT + (uint32_t)(ar * 144 + ac * 16), Al + aoff);
            int br = idx >> 4, bc = idx & 15; // B: 64 rows x 16 chunks
            const size_t boff = (size_t)(k0 + br) * N + bn + bc * 8;
            cp16(base + 2u * TG_AT + (uint32_t)(br * 272 + bc * 16), Bh + boff);
            cp16(base + 2u * TG_AT + TG_BT + (uint32_t)(br * 272 + bc * 16), Bl + boff);
        }
    };

    float acc[2][8][4];
    #pragma unroll
    for (int mi = 0; mi < 2; mi++)
        #pragma unroll
        for (int j = 0; j < 8; j++)
            #pragma unroll
            for (int q = 0; q < 4; q++) acc[mi][j][q] = 0.f;

    const int NC = K >> 6;
    issue(0, 0); CP_COMMIT();

    for (int c = 0; c < NC; c++) {
        const int buf = c & 1;
        const bool more = (c + 1 < NC);
        if (more) { issue((c + 1) << 6, buf ^ 1); CP_COMMIT(); CP_WAIT(1); }
        else      { CP_WAIT(0); }
        __syncthreads();

        const uint32_t base = sb + (uint32_t)buf * TG_BUF;
        #pragma unroll
        for (int ks = 0; ks < 4; ks++) {
            uint32_t afh[2][4], afl[2][4];
            #pragma unroll
            for (int mi = 0; mi < 2; mi++) {
                uint32_t ro = base + (uint32_t)((wm + mi * 16 + (lane & 15)) * 144
                                                + ks * 32 + (lane >> 4) * 16);
                ldsm4(afh[mi], ro);
                ldsm4(afl[mi], ro + TG_AT);
            }
            uint32_t bfh[4][4], bfl[4][4];
            const uint32_t kro = base + 2u * TG_AT
                + (uint32_t)((ks * 16 + (lane & 15)) * 272 + (lane >> 4) * 16);
            #pragma unroll
            for (int nb = 0; nb < 4; nb++) {
                uint32_t no = kro + (uint32_t)((wn + nb * 16) * 2);
                ldsm4t(bfh[nb], no);
                ldsm4t(bfl[nb], no + TG_BT);
            }
            #pragma unroll
            for (int mi = 0; mi < 2; mi++)
                #pragma unroll
                for (int nb = 0; nb < 4; nb++)
                    #pragma unroll
                    for (int hh = 0; hh < 2; hh++) {
                        float (&cc)[4] = acc[mi][nb * 2 + hh];
                        mma_bf16(cc, afh[mi], bfh[nb][2 * hh], bfh[nb][2 * hh + 1]);
                        mma_bf16(cc, afh[mi], bfl[nb][2 * hh], bfl[nb][2 * hh + 1]);
                        mma_bf16(cc, afl[mi], bfh[nb][2 * hh], bfh[nb][2 * hh + 1]);
                    }
        }
        __syncthreads();
    }

    // epilogue
    const int r0 = lane >> 2;
    const int c0 = (lane & 3) << 1;
    #pragma unroll
    for (int mi = 0; mi < 2; mi++) {
        #pragma unroll
        for (int j = 0; j < 8; j++) {
            const int col = bn + wn + j * 8 + c0;
            float bias0 = 0.f, bias1 = 0.f;
            if (bias != nullptr) { bias0 = bias[col]; bias1 = bias[col + 1]; }
            const int row_a = bm + wm + mi * 16 + r0;
            float* Ca = C + (size_t)row_a * N + col;
            float* Cb = C + (size_t)(row_a + 8) * N + col;
            Ca[0] = acc[mi][j][0] + bias0;
            Ca[1] = acc[mi][j][1] + bias1;
            Cb[0] = acc[mi][j][2] + bias0;
            Cb[1] = acc[mi][j][3] + bias1;
        }
    }
}

// ---------------------------------------------------------------------------
// RoPE Q: read fp32 pre-rope Q, write bf16 hi/lo roped Q.
// ---------------------------------------------------------------------------
__global__ void rope_q_kernel(const int* __restrict__ positions,
                              const float* __restrict__ x,
                              __nv_bfloat16* __restrict__ xh,
                              __nv_bfloat16* __restrict__ xl)
{
    int i = blockIdx.x * blockDim.x + threadIdx.x;
    if (i >= TSEQ * NH * 64) return;
    int d = i & 63;
    int rest = i >> 6;
    int hh = rest % NH;
    int t  = rest / NH;

    float pos = (float)positions[t];
    float inv_freq = powf(1.0e6f, -(float)d * (1.0f / 64.0f));
    float s, c;
    sincosf(pos * inv_freq, &s, &c);

    size_t base = (size_t)t * (NH * DH) + (size_t)hh * DH;
    float x1 = x[base + d];
    float x2 = x[base + d + 64];
    float y1 = x1 * c - x2 * s;
    float y2 = x2 * c + x1 * s;
    __nv_bfloat16 h1 = __float2bfloat16(y1);
    __nv_bfloat16 h2 = __float2bfloat16(y2);
    xh[base + d]      = h1;
    xl[base + d]      = __float2bfloat16(y1 - __bfloat162float(h1));
    xh[base + d + 64] = h2;
    xl[base + d + 64] = __float2bfloat16(y2 - __bfloat162float(h2));
}

// ---------------------------------------------------------------------------
// RoPE K: in-place fp32 (for kv_fused output) + bf16 hi/lo.
// ---------------------------------------------------------------------------
__global__ void rope_k_kernel(const int* __restrict__ positions,
                              float* __restrict__ x,
                              __nv_bfloat16* __restrict__ xh,
                              __nv_bfloat16* __restrict__ xl)
{
    int i = blockIdx.x * blockDim.x + threadIdx.x;
    if (i >= TSEQ * NKV * 64) return;
    int d = i & 63;
    int rest = i >> 6;
    int hh = rest % NKV;
    int t  = rest / NKV;

    float pos = (float)positions[t];
    float inv_freq = powf(1.0e6f, -(float)d * (1.0f / 64.0f));
    float s, c;
    sincosf(pos * inv_freq, &s, &c);

    size_t base = (size_t)t * (NKV * DH) + (size_t)hh * DH;
    float x1 = x[base + d];
    float x2 = x[base + d + 64];
    float y1 = x1 * c - x2 * s;
    float y2 = x2 * c + x1 * s;
    x[base + d]      = y1;
    x[base + d + 64] = y2;
    __nv_bfloat16 h1 = __float2bfloat16(y1);
    __nv_bfloat16 h2 = __float2bfloat16(y2);
    xh[base + d]      = h1;
    xl[base + d]      = __float2bfloat16(y1 - __bfloat162float(h1));
    xh[base + d + 64] = h2;
    xl[base + d + 64] = __float2bfloat16(y2 - __bfloat162float(h2));
}

// ---------------------------------------------------------------------------
// MMA flash attention (split bf16 x3 for QK^T and P.V, fp32 accum/softmax).
// Grid (NH, T/64), 128 threads (4 warps, 16 q-rows each).
// ---------------------------------------------------------------------------
#define AT_Q  17408u    // [64][272B]
#define AT_KT 18432u    // [128][144B]  (K transposed: [d][kv])
#define AT_V  17408u    // [64][272B]
#define OFF_QH 0u
#define OFF_QL AT_Q
#define OFF_KTH (2u * AT_Q)
#define OFF_KTL (2u * AT_Q + AT_KT)
#define OFF_VH (2u * AT_Q + 2u * AT_KT)
#define OFF_VL (2u * AT_Q + 2u * AT_KT + AT_V)
#define AT_SMEM (2u * AT_Q + 2u * AT_KT + 2u * AT_V)   // 106496

__global__ __launch_bounds__(128) void attn_mma(
    const __nv_bfloat16* __restrict__ qh, const __nv_bfloat16* __restrict__ ql,
    const __nv_bfloat16* __restrict__ kh, const __nv_bfloat16* __restrict__ kl,
    const __nv_bfloat16* __restrict__ vh, const __nv_bfloat16* __restrict__ vl,
    float* __restrict__ o)
{
    extern __shared__ char sm[];
    const uint32_t sb = smem_u32(sm);
    const int h  = blockIdx.x;
    const int m0 = blockIdx.y << 6;
    const int kvh = h / GRP;
    const int tid = threadIdx.x;
    const int wid = tid >> 5;
    const int lane = tid & 31;
    const int wm = wid << 4;          // 16 q-rows per warp
    const int gID = lane >> 2;
    const int tig = lane & 3;
    const float scale = 0.08838834764831843f;

    // load Q tile (64 x 128) hi/lo
    #pragma unroll
    for (int i = 0; i < 8; i++) {
        int idx = tid + i * 128;          // 0..1023
        int r = idx >> 4, ch = idx & 15;
        const size_t go = (size_t)(m0 + r) * (NH * DH) + (size_t)h * DH + ch * 8;
        *(uint4*)(sm + OFF_QH + r * 272 + ch * 16) = *(const uint4*)(qh + go);
        *(uint4*)(sm + OFF_QL + r * 272 + ch * 16) = *(const uint4*)(ql + go);
    }

    float oacc[16][4];
    #pragma unroll
    for (int j = 0; j < 16; j++)
        #pragma unroll
        for (int q = 0; q < 4; q++) oacc[j][q] = 0.f;
    float m_run0 = -1e30f, m_run1 = -1e30f, l_run0 = 0.f, l_run1 = 0.f;

    const int nblocks = (m0 >> 6) + 1;
    for (int blk = 0; blk < nblocks; blk++) {
        const int n0 = blk << 6;
        __syncthreads();
        // load K^T tile: [d=128][kv=64], transposed scatter
        {
            int kv = tid & 63;
            int half = tid >> 6;      // 0/1
            const size_t kbase = (size_t)(n0 + kv) * (NKV * DH) + (size_t)kvh * DH + half * 64;
            #pragma unroll
            for (int it = 0; it < 8; it++) {
                int d0 = half * 64 + it * 8;
                uint4 vh4 = *(const uint4*)(kh + kbase + it * 8);
                uint4 vl4 = *(const uint4*)(kl + kbase + it * 8);
                const uint32_t* ph = &vh4.x;
                const uint32_t* pl = &vl4.x;
                #pragma unroll
                for (int q = 0; q < 4; q++) {
                    uint32_t uh = ph[q], ul = pl[q];
                    *(uint16_t*)(sm + OFF_KTH + (d0 + 2 * q) * 144 + kv * 2)     = (uint16_t)(uh & 0xFFFF);
                    *(uint16_t*)(sm + OFF_KTH + (d0 + 2 * q + 1) * 144 + kv * 2) = (uint16_t)(uh >> 16);
                    *(uint16_t*)(sm + OFF_KTL + (d0 + 2 * q) * 144 + kv * 2)     = (uint16_t)(ul & 0xFFFF);
                    *(uint16_t*)(sm + OFF_KTL + (d0 + 2 * q + 1) * 144 + kv * 2) = (uint16_t)(ul >> 16);
                }
            }
        }
        // load V tile: [kv=64][dh=128]
        #pragma unroll
        for (int i = 0; i < 8; i++) {
            int idx = tid + i * 128;
            int r = idx >> 4, ch = idx & 15;
            const size_t go = (size_t)(n0 + r) * (NKV * DH) + (size_t)kvh * DH + ch * 8;
            *(uint4*)(sm + OFF_VH + r * 272 + ch * 16) = *(const uint4*)(vh + go);
            *(uint4*)(sm + OFF_VL + r * 272 + ch * 16) = *(const uint4*)(vl + go);
        }
        __syncthreads();

        // ---- S = Q K^T (split x3) ----
        float sacc[8][4];
        #pragma unroll
        for (int j = 0; j < 8; j++)
            #pragma unroll
            for (int q = 0; q < 4; q++) sacc[j][q] = 0.f;

        #pragma unroll
        for (int ks = 0; ks < 8; ks++) {
            uint32_t aH[4], aL[4];
            uint32_t ro = sb + OFF_QH + (uint32_t)((wm + (lane & 15)) * 272
                                                   + ks * 32 + (lane >> 4) * 16);
            ldsm4(aH, ro);
            ldsm4(aL, ro + AT_Q);
            const uint32_t kro = sb + OFF_KTH
                + (uint32_t)((ks * 16 + (lane & 15)) * 144 + (lane >> 4) * 16);
            #pragma unroll
            for (int nb = 0; nb < 4; nb++) {
                uint32_t bh4[4], bl4[4];
                uint32_t no = kro + (uint32_t)(nb * 32);
                ldsm4t(bh4, no);
                ldsm4t(bl4, no + AT_KT);
                #pragma unroll
                for (int hh = 0; hh < 2; hh++) {
                    float (&cc)[4] = sacc[nb * 2 + hh];
                    mma_bf16(cc, aH, bh4[2 * hh], bh4[2 * hh + 1]);
                    mma_bf16(cc, aH, bl4[2 * hh], bl4[2 * hh + 1]);
                    mma_bf16(cc, aL, bh4[2 * hh], bh4[2 * hh + 1]);
                }
            }
        }

        // ---- online softmax (rows r0 = gID, r1 = gID+8 within warp tile) ----
        const bool diag = (blk == nblocks - 1);
        const int row0 = m0 + wm + gID;
        const int row1 = row0 + 8;
        float mx0 = -1e30f, mx1 = -1e30f;
        #pragma unroll
        for (int nb = 0; nb < 8; nb++) {
            #pragma unroll
            for (int j = 0; j < 2; j++) {
                const int col = n0 + nb * 8 + tig * 2 + j;
                float s0 = sacc[nb][j] * scale;
                float s1 = sacc[nb][2 + j] * scale;
                if (diag && col > row0) s0 = -1e30f;
                if (diag && col > row1) s1 = -1e30f;
                sacc[nb][j] = s0;
                sacc[nb][2 + j] = s1;
                mx0 = fmaxf(mx0, s0);
                mx1 = fmaxf(mx1, s1);
            }
        }
        #pragma unroll
        for (int off = 1; off <= 2; off <<= 1) {
            mx0 = fmaxf(mx0, __shfl_xor_sync(0xffffffffu, mx0, off));
            mx1 = fmaxf(mx1, __shfl_xor_sync(0xffffffffu, mx1, off));
        }
        float mn0 = fmaxf(m_run0, mx0);
        float mn1 = fmaxf(m_run1, mx1);
        float cf0 = __expf(m_run0 - mn0);
        float cf1 = __expf(m_run1 - mn1);
        m_run0 = mn0; m_run1 = mn1;
        float su0 = 0.f, su1 = 0.f;
        #pragma unroll
        for (int nb = 0; nb < 8; nb++) {
            #pragma unroll
            for (int j = 0; j < 2; j++) {
                float p0 = __expf(sacc[nb][j] - mn0);
                float p1 = __expf(sacc[nb][2 + j] - mn1);
                sacc[nb][j] = p0;
                sacc[nb][2 + j] = p1;
                su0 += p0;
                su1 += p1;
            }
        }
        #pragma unroll
        for (int off = 1; off <= 2; off <<= 1) {
            su0 += __shfl_xor_sync(0xffffffffu, su0, off);
            su1 += __shfl_xor_sync(0xffffffffu, su1, off);
        }
        l_run0 = l_run0 * cf0 + su0;
        l_run1 = l_run1 * cf1 + su1;
        #pragma unroll
        for (int j = 0; j < 16; j++) {
            oacc[j][0] *= cf0;
            oacc[j][1] *= cf0;
            oacc[j][2] *= cf1;
            oacc[j][3] *= cf1;
        }

        // ---- O += P V (split x3; P packed register-direct) ----
        #pragma unroll
        for (int ks = 0; ks < 4; ks++) {
            uint32_t ph[4], pl[4];
            split_pack(sacc[2 * ks][0],     sacc[2 * ks][1],     ph[0], pl[0]);
            split_pack(sacc[2 * ks][2],     sacc[2 * ks][3],     ph[1], pl[1]);
            split_pack(sacc[2 * ks + 1][0], sacc[2 * ks + 1][1], ph[2], pl[2]);
            split_pack(sacc[2 * ks + 1][2], sacc[2 * ks + 1][3], ph[3], pl[3]);
            const uint32_t vro = sb + OFF_VH
                + (uint32_t)((ks * 16 + (lane & 15)) * 272 + (lane >> 4) * 16);
            #pragma unroll
            for (int nbv = 0; nbv < 8; nbv++) {
                uint32_t vbh[4], vbl[4];
                uint32_t no = vro + (uint32_t)(nbv * 32);
                ldsm4t(vbh, no);
                ldsm4t(vbl, no + AT_V);
                #pragma unroll
                for (int hh = 0; hh < 2; hh++) {
                    float (&cc)[4] = oacc[nbv * 2 + hh];
                    mma_bf16(cc, ph, vbh[2 * hh], vbh[2 * hh + 1]);
                    mma_bf16(cc, ph, vbl[2 * hh], vbl[2 * hh + 1]);
                    mma_bf16(cc, pl, vbh[2 * hh], vbh[2 * hh + 1]);
                }
            }
        }
    }

    // epilogue
    const float inv0 = 1.0f / l_run0;
    const float inv1 = 1.0f / l_run1;
    const int row0 = m0 + wm + gID;
    #pragma unroll
    for (int onb = 0; onb < 16; onb++) {
        const int col = h * DH + onb * 8 + tig * 2;
        float* p0 = o + (size_t)row0 * (NH * DH) + col;
        float* p1 = o + (size_t)(row0 + 8) * (NH * DH) + col;
        p0[0] = oacc[onb][0] * inv0;
        p0[1] = oacc[onb][1] * inv0;
        p1[0] = oacc[onb][2] * inv1;
        p1[1] = oacc[onb][3] * inv1;
    }
}

// ---------------------------------------------------------------------------
extern "C" void kernel_launch(void* const* d_in, const int* in_sizes, int n_in,
                              void* d_out, int out_size)
{
    const int*   positions = (const int*)d_in[0];
    const float* hs = (const float*)d_in[1];
    const float* Wq = (const float*)d_in[2];
    const float* bq = (const float*)d_in[3];
    const float* Wk = (const float*)d_in[4];
    const float* bk = (const float*)d_in[5];
    const float* Wv = (const float*)d_in[6];
    const float* bv = (const float*)d_in[7];
    const float* Wo = (const float*)d_in[8];

    float* out  = (float*)d_out;
    float* kout = out + (size_t)TSEQ * HID;
    float* vout = kout + (size_t)TSEQ * NKV * DH;

    float *qbuf, *abuf;
    __nv_bfloat16 *hsh, *hsl, *wqh, *wql, *wkh, *wkl, *wvh, *wvl, *woh, *wol;
    __nv_bfloat16 *qqh, *qql, *kkh, *kkl, *vvh, *vvl, *aah, *aal;
    cudaGetSymbolAddress((void**)&qbuf, g_q);
    cudaGetSymbolAddress((void**)&abuf, g_attn);
    cudaGetSymbolAddress((void**)&hsh, g_hsh);  cudaGetSymbolAddress((void**)&hsl, g_hsl);
    cudaGetSymbolAddress((void**)&wqh, g_wqh);  cudaGetSymbolAddress((void**)&wql, g_wql);
    cudaGetSymbolAddress((void**)&wkh, g_wkh);  cudaGetSymbolAddress((void**)&wkl, g_wkl);
    cudaGetSymbolAddress((void**)&wvh, g_wvh);  cudaGetSymbolAddress((void**)&wvl, g_wvl);
    cudaGetSymbolAddress((void**)&woh, g_woh);  cudaGetSymbolAddress((void**)&wol, g_wol);
    cudaGetSymbolAddress((void**)&qqh, g_qh);   cudaGetSymbolAddress((void**)&qql, g_ql);
    cudaGetSymbolAddress((void**)&kkh, g_kh);   cudaGetSymbolAddress((void**)&kkl, g_kl);
    cudaGetSymbolAddress((void**)&vvh, g_vh);   cudaGetSymbolAddress((void**)&vvl, g_vl);
    cudaGetSymbolAddress((void**)&aah, g_ah);   cudaGetSymbolAddress((void**)&aal, g_al);

    cudaFuncSetAttribute(tgemm2, cudaFuncAttributeMaxDynamicSharedMemorySize, (int)TG_SMEM);
    cudaFuncSetAttribute(attn_mma, cudaFuncAttributeMaxDynamicSharedMemorySize, (int)AT_SMEM);

    // 1. pre-split inputs
    {
        int n4;
        n4 = TSEQ * HID / 4;
        convert_split<<<(n4 + 255) / 256, 256>>>((const float4*)hs, (uint2*)hsh, (uint2*)hsl, n4);
        n4 = HID * NH * DH / 4;
        convert_split<<<(n4 + 255) / 256, 256>>>((const float4*)Wq, (uint2*)wqh, (uint2*)wql, n4);
        n4 = HID * NKV * DH / 4;
        convert_split<<<(n4 + 255) / 256, 256>>>((const float4*)Wk, (uint2*)wkh, (uint2*)wkl, n4);
        convert_split<<<(n4 + 255) / 256, 256>>>((const float4*)Wv, (uint2*)wvh, (uint2*)wvl, n4);
        n4 = NH * DH * HID / 4;
        convert_split<<<(n4 + 255) / 256, 256>>>((const float4*)Wo, (uint2*)woh, (uint2*)wol, n4);
    }

    // 2. projections
    tgemm2<<<dim3(NH * DH / 128, TSEQ / 128), 256, TG_SMEM>>>(hsh, hsl, wqh, wql, bq, qbuf, TSEQ, NH * DH, HID);
    tgemm2<<<dim3(NKV * DH / 128, TSEQ / 128), 256, TG_SMEM>>>(hsh, hsl, wkh, wkl, bk, kout, TSEQ, NKV * DH, HID);
    tgemm2<<<dim3(NKV * DH / 128, TSEQ / 128), 256, TG_SMEM>>>(hsh, hsl, wvh, wvl, bv, vout, TSEQ, NKV * DH, HID);

    // 3. rope (emit bf16 splits; K also fp32 in-place for kv_fused)
    rope_q_kernel<<<(TSEQ * NH * 64 + 255) / 256, 256>>>(positions, qbuf, qqh, qql);
    rope_k_kernel<<<(TSEQ * NKV * 64 + 255) / 256, 256>>>(positions, kout, kkh, kkl);

    // 4. split V
    {
        int n4 = TSEQ * NKV * DH / 4;
        convert_split<<<(n4 + 255) / 256, 256>>>((const float4*)vout, (uint2*)vvh, (uint2*)vvl, n4);
    }

    // 5. attention
    attn_mma<<<dim3(NH, TSEQ / 64), 128, AT_SMEM>>>(qqh, qql, kkh, kkl, vvh, vvl, abuf);

    // 6. split attention output, O projection
    {
        int n4 = TSEQ * NH * DH / 4;
        convert_split<<<(n4 + 255) / 256, 256>>>((const float4*)abuf, (uint2*)aah, (uint2*)aal, n4);
    }
    tgemm2<<<dim3(HID / 128, TSEQ / 128), 256, TG_SMEM>>>(aah, aal, woh, wol, nullptr, out, TSEQ, HID, NH * DH);
}

// round 6
// speedup vs baseline: 2.9990x; 1.0241x over previous
#include <cuda_runtime.h>
#include <cuda_bf16.h>
#include <math.h>
#include <stdint.h>

#define TSEQ 2048
#define HID  4096
#define NH   32
#define NKV  8
#define DH   128
#define GRP  (NH / NKV)

// ---------------------------------------------------------------------------
// Scratch (allocation-free rule: __device__ globals)
// ---------------------------------------------------------------------------
__device__ float g_q[(size_t)TSEQ * NH * DH];      // fp32 Q (pre-rope)
__device__ __nv_bfloat16 g_hsh[(size_t)TSEQ * HID],      g_hsl[(size_t)TSEQ * HID];
__device__ __nv_bfloat16 g_wqh[(size_t)HID * NH * DH],   g_wql[(size_t)HID * NH * DH];
__device__ __nv_bfloat16 g_wkh[(size_t)HID * NKV * DH],  g_wkl[(size_t)HID * NKV * DH];
__device__ __nv_bfloat16 g_wvh[(size_t)HID * NKV * DH],  g_wvl[(size_t)HID * NKV * DH];
__device__ __nv_bfloat16 g_woh[(size_t)NH * DH * HID],   g_wol[(size_t)NH * DH * HID];
__device__ __nv_bfloat16 g_qh[(size_t)TSEQ * NH * DH],   g_ql[(size_t)TSEQ * NH * DH];
__device__ __nv_bfloat16 g_kh[(size_t)TSEQ * NKV * DH],  g_kl[(size_t)TSEQ * NKV * DH];
__device__ __nv_bfloat16 g_vh[(size_t)TSEQ * NKV * DH],  g_vl[(size_t)TSEQ * NKV * DH];
__device__ __nv_bfloat16 g_ah[(size_t)TSEQ * NH * DH],   g_al[(size_t)TSEQ * NH * DH];

// ---------------------------------------------------------------------------
// helpers
// ---------------------------------------------------------------------------
__device__ __forceinline__ uint32_t smem_u32(const void* p) {
    uint32_t a;
    asm("{ .reg .u64 t; cvta.to.shared.u64 t, %1; cvt.u32.u64 %0, t; }"
        : "=r"(a) : "l"(p));
    return a;
}
__device__ __forceinline__ uint32_t cvt_bf16x2(float hi, float lo) {
    uint32_t r;
    asm("cvt.rn.bf16x2.f32 %0, %1, %2;" : "=r"(r) : "f"(hi), "f"(lo));
    return r;
}
__device__ __forceinline__ void ldsm4(uint32_t (&r)[4], uint32_t a) {
    asm volatile("ldmatrix.sync.aligned.m8n8.x4.shared.b16 {%0,%1,%2,%3}, [%4];"
        : "=r"(r[0]), "=r"(r[1]), "=r"(r[2]), "=r"(r[3]) : "r"(a));
}
__device__ __forceinline__ void ldsm4t(uint32_t (&r)[4], uint32_t a) {
    asm volatile("ldmatrix.sync.aligned.m8n8.x4.trans.shared.b16 {%0,%1,%2,%3}, [%4];"
        : "=r"(r[0]), "=r"(r[1]), "=r"(r[2]), "=r"(r[3]) : "r"(a));
}
__device__ __forceinline__ void mma_bf16(float (&c)[4], const uint32_t (&a)[4],
                                         uint32_t b0, uint32_t b1) {
    asm volatile("mma.sync.aligned.m16n8k16.row.col.f32.bf16.bf16.f32 "
        "{%0,%1,%2,%3}, {%4,%5,%6,%7}, {%8,%9}, {%0,%1,%2,%3};"
        : "+f"(c[0]), "+f"(c[1]), "+f"(c[2]), "+f"(c[3])
        : "r"(a[0]), "r"(a[1]), "r"(a[2]), "r"(a[3]), "r"(b0), "r"(b1));
}
__device__ __forceinline__ void cp16(uint32_t dst, const void* src) {
    asm volatile("cp.async.cg.shared.global [%0], [%1], 16;" :: "r"(dst), "l"(src));
}
#define CP_COMMIT() asm volatile("cp.async.commit_group;" ::: "memory")
#define CP_WAIT(n)  asm volatile("cp.async.wait_group %0;" :: "n"(n) : "memory")

__device__ __forceinline__ void split_pack(float x, float y, uint32_t& hi, uint32_t& lo) {
    hi = cvt_bf16x2(y, x);
    float rx = x - __uint_as_float(hi << 16);
    float ry = y - __uint_as_float(hi & 0xFFFF0000u);
    lo = cvt_bf16x2(ry, rx);
}

// ---------------------------------------------------------------------------
// convert fp32 -> bf16 hi + bf16 lo, 8 elements per thread
// ---------------------------------------------------------------------------
__global__ void convert_split(const float4* __restrict__ in,
                              uint2* __restrict__ hi, uint2* __restrict__ lo, int n4)
{
    int i = (blockIdx.x * blockDim.x + threadIdx.x) * 2;
    if (i >= n4) return;
    float4 v0 = in[i];
    float4 v1 = in[i + 1];
    uint32_t h0, l0, h1, l1, h2, l2, h3, l3;
    split_pack(v0.x, v0.y, h0, l0);
    split_pack(v0.z, v0.w, h1, l1);
    split_pack(v1.x, v1.y, h2, l2);
    split_pack(v1.z, v1.w, h3, l3);
    hi[i]     = make_uint2(h0, h1);
    lo[i]     = make_uint2(l0, l1);
    hi[i + 1] = make_uint2(h2, h3);
    lo[i + 1] = make_uint2(l2, l3);
}

// ---------------------------------------------------------------------------
// Tensor-core GEMM from pre-split bf16 hi/lo. C = A@B (+bias), fp32 out,
// optional bf16 hi/lo split outputs. CTA 128x128, K-chunk 64, 3-stage
// cp.async pipeline. 256 threads, 8 warps (4Mx2N).
// ---------------------------------------------------------------------------
#define TG_AT 18432u            // A tile [128][144B]
#define TG_BT 17408u            // B tile [64][272B]
#define TG_BUF (2u * TG_AT + 2u * TG_BT)    // 71680
#define TG_SMEM (3u * TG_BUF)               // 215040

__global__ __launch_bounds__(256, 1) void tgemm2(
    const __nv_bfloat16* __restrict__ Ah, const __nv_bfloat16* __restrict__ Al,
    const __nv_bfloat16* __restrict__ Bh, const __nv_bfloat16* __restrict__ Bl,
    const float* __restrict__ bias, float* __restrict__ C,
    __nv_bfloat16* __restrict__ Ch, __nv_bfloat16* __restrict__ Cl,
    int M, int N, int K)
{
    extern __shared__ char sm[];
    const uint32_t sb = smem_u32(sm);

    const int tid  = threadIdx.x;
    const int wid  = tid >> 5;
    const int lane = tid & 31;
    const int bm = blockIdx.y << 7;
    const int bn = blockIdx.x << 7;
    const int wm = (wid >> 1) << 5;
    const int wn = (wid & 1) << 6;

    auto issue = [&](int k0, int buf) {
        const uint32_t base = sb + (uint32_t)buf * TG_BUF;
        #pragma unroll
        for (int i = 0; i < 4; i++) {
            int idx = tid + i * 256;
            int ar = idx >> 3, ac = idx & 7;
            const size_t aoff = (size_t)(bm + ar) * K + k0 + ac * 8;
            cp16(base + (uint32_t)(ar * 144 + ac * 16), Ah + aoff);
            cp16(base + TG_AT + (uint32_t)(ar * 144 + ac * 16), Al + aoff);
            int br = idx >> 4, bc = idx & 15;
            const size_t boff = (size_t)(k0 + br) * N + bn + bc * 8;
            cp16(base + 2u * TG_AT + (uint32_t)(br * 272 + bc * 16), Bh + boff);
            cp16(base + 2u * TG_AT + TG_BT + (uint32_t)(br * 272 + bc * 16), Bl + boff);
        }
    };

    float acc[2][8][4];
    #pragma unroll
    for (int mi = 0; mi < 2; mi++)
        #pragma unroll
        for (int j = 0; j < 8; j++)
            #pragma unroll
            for (int q = 0; q < 4; q++) acc[mi][j][q] = 0.f;

    const int NC = K >> 6;
    issue(0, 0); CP_COMMIT();
    if (NC > 1) { issue(64, 1); CP_COMMIT(); }

    for (int c = 0; c < NC; c++) {
        if (c + 1 < NC) { CP_WAIT(1); } else { CP_WAIT(0); }
        __syncthreads();
        if (c + 2 < NC) { issue((c + 2) << 6, (c + 2) % 3); CP_COMMIT(); }

        const uint32_t base = sb + (uint32_t)(c % 3) * TG_BUF;
        #pragma unroll
        for (int ks = 0; ks < 4; ks++) {
            uint32_t afh[2][4], afl[2][4];
            #pragma unroll
            for (int mi = 0; mi < 2; mi++) {
                uint32_t ro = base + (uint32_t)((wm + mi * 16 + (lane & 15)) * 144
                                                + ks * 32 + (lane >> 4) * 16);
                ldsm4(afh[mi], ro);
                ldsm4(afl[mi], ro + TG_AT);
            }
            uint32_t bfh[4][4], bfl[4][4];
            const uint32_t kro = base + 2u * TG_AT
                + (uint32_t)((ks * 16 + (lane & 15)) * 272 + (lane >> 4) * 16);
            #pragma unroll
            for (int nb = 0; nb < 4; nb++) {
                uint32_t no = kro + (uint32_t)((wn + nb * 16) * 2);
                ldsm4t(bfh[nb], no);
                ldsm4t(bfl[nb], no + TG_BT);
            }
            #pragma unroll
            for (int mi = 0; mi < 2; mi++)
                #pragma unroll
                for (int nb = 0; nb < 4; nb++)
                    #pragma unroll
                    for (int hh = 0; hh < 2; hh++) {
                        float (&cc)[4] = acc[mi][nb * 2 + hh];
                        mma_bf16(cc, afh[mi], bfh[nb][2 * hh], bfh[nb][2 * hh + 1]);
                        mma_bf16(cc, afh[mi], bfl[nb][2 * hh], bfl[nb][2 * hh + 1]);
                        mma_bf16(cc, afl[mi], bfh[nb][2 * hh], bfh[nb][2 * hh + 1]);
                    }
        }
    }

    // epilogue
    const int r0 = lane >> 2;
    const int c0 = (lane & 3) << 1;
    #pragma unroll
    for (int mi = 0; mi < 2; mi++) {
        #pragma unroll
        for (int j = 0; j < 8; j++) {
            const int col = bn + wn + j * 8 + c0;
            float bias0 = 0.f, bias1 = 0.f;
            if (bias != nullptr) { bias0 = bias[col]; bias1 = bias[col + 1]; }
            const int row_a = bm + wm + mi * 16 + r0;
            const int row_b = row_a + 8;
            float va0 = acc[mi][j][0] + bias0, va1 = acc[mi][j][1] + bias1;
            float vb0 = acc[mi][j][2] + bias0, vb1 = acc[mi][j][3] + bias1;
            float* Ca = C + (size_t)row_a * N + col;
            float* Cb = C + (size_t)row_b * N + col;
            Ca[0] = va0; Ca[1] = va1;
            Cb[0] = vb0; Cb[1] = vb1;
            if (Ch != nullptr) {
                uint32_t hh_, ll_;
                split_pack(va0, va1, hh_, ll_);
                *(uint32_t*)(Ch + (size_t)row_a * N + col) = hh_;
                *(uint32_t*)(Cl + (size_t)row_a * N + col) = ll_;
                split_pack(vb0, vb1, hh_, ll_);
                *(uint32_t*)(Ch + (size_t)row_b * N + col) = hh_;
                *(uint32_t*)(Cl + (size_t)row_b * N + col) = ll_;
            }
        }
    }
}

// ---------------------------------------------------------------------------
// RoPE Q: fp32 pre-rope Q -> bf16 hi/lo roped Q, pre-scaled by 1/sqrt(D).
// ---------------------------------------------------------------------------
__global__ void rope_q_kernel(const int* __restrict__ positions,
                              const float* __restrict__ x,
                              __nv_bfloat16* __restrict__ xh,
                              __nv_bfloat16* __restrict__ xl)
{
    int i = blockIdx.x * blockDim.x + threadIdx.x;
    if (i >= TSEQ * NH * 64) return;
    int d = i & 63;
    int rest = i >> 6;
    int hh = rest % NH;
    int t  = rest / NH;

    const float scale = 0.08838834764831843f;
    float pos = (float)positions[t];
    float inv_freq = powf(1.0e6f, -(float)d * (1.0f / 64.0f));
    float s, c;
    sincosf(pos * inv_freq, &s, &c);

    size_t base = (size_t)t * (NH * DH) + (size_t)hh * DH;
    float x1 = x[base + d];
    float x2 = x[base + d + 64];
    float y1 = (x1 * c - x2 * s) * scale;
    float y2 = (x2 * c + x1 * s) * scale;
    __nv_bfloat16 h1 = __float2bfloat16(y1);
    __nv_bfloat16 h2 = __float2bfloat16(y2);
    xh[base + d]      = h1;
    xl[base + d]      = __float2bfloat16(y1 - __bfloat162float(h1));
    xh[base + d + 64] = h2;
    xl[base + d + 64] = __float2bfloat16(y2 - __bfloat162float(h2));
}

// ---------------------------------------------------------------------------
// RoPE K: in-place fp32 (kv_fused output) + bf16 hi/lo.
// ---------------------------------------------------------------------------
__global__ void rope_k_kernel(const int* __restrict__ positions,
                              float* __restrict__ x,
                              __nv_bfloat16* __restrict__ xh,
                              __nv_bfloat16* __restrict__ xl)
{
    int i = blockIdx.x * blockDim.x + threadIdx.x;
    if (i >= TSEQ * NKV * 64) return;
    int d = i & 63;
    int rest = i >> 6;
    int hh = rest % NKV;
    int t  = rest / NKV;

    float pos = (float)positions[t];
    float inv_freq = powf(1.0e6f, -(float)d * (1.0f / 64.0f));
    float s, c;
    sincosf(pos * inv_freq, &s, &c);

    size_t base = (size_t)t * (NKV * DH) + (size_t)hh * DH;
    float x1 = x[base + d];
    float x2 = x[base + d + 64];
    float y1 = x1 * c - x2 * s;
    float y2 = x2 * c + x1 * s;
    x[base + d]      = y1;
    x[base + d + 64] = y2;
    __nv_bfloat16 h1 = __float2bfloat16(y1);
    __nv_bfloat16 h2 = __float2bfloat16(y2);
    xh[base + d]      = h1;
    xl[base + d]      = __float2bfloat16(y1 - __bfloat162float(h1));
    xh[base + d + 64] = h2;
    xl[base + d + 64] = __float2bfloat16(y2 - __bfloat162float(h2));
}

// ---------------------------------------------------------------------------
// MMA flash attention: 128 q-rows per CTA, 256 threads (8 warps x 16 rows).
// Q pre-scaled. Split bf16 x3 for QK^T and P.V. Writes bf16 hi/lo output.
// Grid (NH, T/128).
// ---------------------------------------------------------------------------
#define A2_Q  34816u    // [128][272B]
#define A2_KT 18432u    // [128][144B]
#define A2_V  17408u    // [64][272B]
#define O_QH 0u
#define O_QL A2_Q
#define O_KTH (2u * A2_Q)
#define O_KTL (2u * A2_Q + A2_KT)
#define O_VH  (2u * A2_Q + 2u * A2_KT)
#define O_VL  (2u * A2_Q + 2u * A2_KT + A2_V)
#define A2_SMEM (2u * A2_Q + 2u * A2_KT + 2u * A2_V)   // 141312

__global__ __launch_bounds__(256, 1) void attn_mma(
    const __nv_bfloat16* __restrict__ qh, const __nv_bfloat16* __restrict__ ql,
    const __nv_bfloat16* __restrict__ kh, const __nv_bfloat16* __restrict__ kl,
    const __nv_bfloat16* __restrict__ vh, const __nv_bfloat16* __restrict__ vl,
    __nv_bfloat16* __restrict__ oh, __nv_bfloat16* __restrict__ ol)
{
    extern __shared__ char sm[];
    const uint32_t sb = smem_u32(sm);
    const int h  = blockIdx.x;
    const int m0 = blockIdx.y << 7;
    const int kvh = h / GRP;
    const int tid = threadIdx.x;
    const int wid = tid >> 5;
    const int lane = tid & 31;
    const int wm = wid << 4;          // 16 q-rows per warp
    const int gID = lane >> 2;
    const int tig = lane & 3;

    // load Q tile (128 x 128) hi/lo
    #pragma unroll
    for (int i = 0; i < 8; i++) {
        int idx = tid + i * 256;
        int r = idx >> 4, ch = idx & 15;
        const size_t go = (size_t)(m0 + r) * (NH * DH) + (size_t)h * DH + ch * 8;
        *(uint4*)(sm + O_QH + r * 272 + ch * 16) = *(const uint4*)(qh + go);
        *(uint4*)(sm + O_QL + r * 272 + ch * 16) = *(const uint4*)(ql + go);
    }

    float oacc[16][4];
    #pragma unroll
    for (int j = 0; j < 16; j++)
        #pragma unroll
        for (int q = 0; q < 4; q++) oacc[j][q] = 0.f;
    float m_run0 = -1e30f, m_run1 = -1e30f, l_run0 = 0.f, l_run1 = 0.f;

    const int row0 = m0 + wm + gID;
    const int row1 = row0 + 8;
    const int warp_max_row = m0 + wm + 15;

    const int nblocks = (m0 >> 6) + 2;
    for (int blk = 0; blk < nblocks; blk++) {
        const int n0 = blk << 6;
        __syncthreads();
        // K^T tile scatter: [d=128][kv=64]
        {
            int kv = tid & 63;
            int quad = tid >> 6;      // 0..3, 32 d-cols each
            const size_t kbase = (size_t)(n0 + kv) * (NKV * DH) + (size_t)kvh * DH + quad * 32;
            #pragma unroll
            for (int it = 0; it < 4; it++) {
                int d0 = quad * 32 + it * 8;
                uint4 vh4 = *(const uint4*)(kh + kbase + it * 8);
                uint4 vl4 = *(const uint4*)(kl + kbase + it * 8);
                const uint32_t* ph_ = &vh4.x;
                const uint32_t* pl_ = &vl4.x;
                #pragma unroll
                for (int q = 0; q < 4; q++) {
                    uint32_t uh = ph_[q], ul = pl_[q];
                    *(uint16_t*)(sm + O_KTH + (d0 + 2 * q) * 144 + kv * 2)     = (uint16_t)(uh & 0xFFFF);
                    *(uint16_t*)(sm + O_KTH + (d0 + 2 * q + 1) * 144 + kv * 2) = (uint16_t)(uh >> 16);
                    *(uint16_t*)(sm + O_KTL + (d0 + 2 * q) * 144 + kv * 2)     = (uint16_t)(ul & 0xFFFF);
                    *(uint16_t*)(sm + O_KTL + (d0 + 2 * q + 1) * 144 + kv * 2) = (uint16_t)(ul >> 16);
                }
            }
        }
        // V tile: [kv=64][dh=128]
        #pragma unroll
        for (int i = 0; i < 4; i++) {
            int idx = tid + i * 256;
            int r = idx >> 4, ch = idx & 15;
            const size_t go = (size_t)(n0 + r) * (NKV * DH) + (size_t)kvh * DH + ch * 8;
            *(uint4*)(sm + O_VH + r * 272 + ch * 16) = *(const uint4*)(vh + go);
            *(uint4*)(sm + O_VL + r * 272 + ch * 16) = *(const uint4*)(vl + go);
        }
        __syncthreads();

        if (n0 > warp_max_row) continue;   // block fully above this warp's diagonal

        // ---- S = Q K^T (split x3) ----
        float sacc[8][4];
        #pragma unroll
        for (int j = 0; j < 8; j++)
            #pragma unroll
            for (int q = 0; q < 4; q++) sacc[j][q] = 0.f;

        #pragma unroll
        for (int ks = 0; ks < 8; ks++) {
            uint32_t aH[4], aL[4];
            uint32_t ro = sb + O_QH + (uint32_t)((wm + (lane & 15)) * 272
                                                 + ks * 32 + (lane >> 4) * 16);
            ldsm4(aH, ro);
            ldsm4(aL, ro + A2_Q);
            const uint32_t kro = sb + O_KTH
                + (uint32_t)((ks * 16 + (lane & 15)) * 144 + (lane >> 4) * 16);
            #pragma unroll
            for (int nb = 0; nb < 4; nb++) {
                uint32_t bh4[4], bl4[4];
                uint32_t no = kro + (uint32_t)(nb * 32);
                ldsm4t(bh4, no);
                ldsm4t(bl4, no + A2_KT);
                #pragma unroll
                for (int hh = 0; hh < 2; hh++) {
                    float (&cc)[4] = sacc[nb * 2 + hh];
                    mma_bf16(cc, aH, bh4[2 * hh], bh4[2 * hh + 1]);
                    mma_bf16(cc, aH, bl4[2 * hh], bl4[2 * hh + 1]);
                    mma_bf16(cc, aL, bh4[2 * hh], bh4[2 * hh + 1]);
                }
            }
        }

        // ---- online softmax (Q pre-scaled; mask applied unconditionally) ----
        float mx0 = -1e30f, mx1 = -1e30f;
        #pragma unroll
        for (int nb = 0; nb < 8; nb++) {
            #pragma unroll
            for (int j = 0; j < 2; j++) {
                const int col = n0 + nb * 8 + tig * 2 + j;
                float s0 = sacc[nb][j];
                float s1 = sacc[nb][2 + j];
                if (col > row0) s0 = -1e30f;
                if (col > row1) s1 = -1e30f;
                sacc[nb][j] = s0;
                sacc[nb][2 + j] = s1;
                mx0 = fmaxf(mx0, s0);
                mx1 = fmaxf(mx1, s1);
            }
        }
        #pragma unroll
        for (int off = 1; off <= 2; off <<= 1) {
            mx0 = fmaxf(mx0, __shfl_xor_sync(0xffffffffu, mx0, off));
            mx1 = fmaxf(mx1, __shfl_xor_sync(0xffffffffu, mx1, off));
        }
        float mn0 = fmaxf(m_run0, mx0);
        float mn1 = fmaxf(m_run1, mx1);
        float cf0 = __expf(m_run0 - mn0);
        float cf1 = __expf(m_run1 - mn1);
        m_run0 = mn0; m_run1 = mn1;
        float su0 = 0.f, su1 = 0.f;
        #pragma unroll
        for (int nb = 0; nb < 8; nb++) {
            #pragma unroll
            for (int j = 0; j < 2; j++) {
                float p0 = __expf(sacc[nb][j] - mn0);
                float p1 = __expf(sacc[nb][2 + j] - mn1);
                sacc[nb][j] = p0;
                sacc[nb][2 + j] = p1;
                su0 += p0;
                su1 += p1;
            }
        }
        #pragma unroll
        for (int off = 1; off <= 2; off <<= 1) {
            su0 += __shfl_xor_sync(0xffffffffu, su0, off);
            su1 += __shfl_xor_sync(0xffffffffu, su1, off);
        }
        l_run0 = l_run0 * cf0 + su0;
        l_run1 = l_run1 * cf1 + su1;
        #pragma unroll
        for (int j = 0; j < 16; j++) {
            oacc[j][0] *= cf0;
            oacc[j][1] *= cf0;
            oacc[j][2] *= cf1;
            oacc[j][3] *= cf1;
        }

        // ---- O += P V (split x3; P packed register-direct) ----
        #pragma unroll
        for (int ks = 0; ks < 4; ks++) {
            uint32_t ph[4], pl[4];
            split_pack(sacc[2 * ks][0],     sacc[2 * ks][1],     ph[0], pl[0]);
            split_pack(sacc[2 * ks][2],     sacc[2 * ks][3],     ph[1], pl[1]);
            split_pack(sacc[2 * ks + 1][0], sacc[2 * ks + 1][1], ph[2], pl[2]);
            split_pack(sacc[2 * ks + 1][2], sacc[2 * ks + 1][3], ph[3], pl[3]);
            const uint32_t vro = sb + O_VH
                + (uint32_t)((ks * 16 + (lane & 15)) * 272 + (lane >> 4) * 16);
            #pragma unroll
            for (int nbv = 0; nbv < 8; nbv++) {
                uint32_t vbh[4], vbl[4];
                uint32_t no = vro + (uint32_t)(nbv * 32);
                ldsm4t(vbh, no);
                ldsm4t(vbl, no + A2_V);
                #pragma unroll
                for (int hh = 0; hh < 2; hh++) {
                    float (&cc)[4] = oacc[nbv * 2 + hh];
                    mma_bf16(cc, ph, vbh[2 * hh], vbh[2 * hh + 1]);
                    mma_bf16(cc, ph, vbl[2 * hh], vbl[2 * hh + 1]);
                    mma_bf16(cc, pl, vbh[2 * hh], vbh[2 * hh + 1]);
                }
            }
        }
    }

    // epilogue: write bf16 hi/lo split of normalized output
    const float inv0 = 1.0f / l_run0;
    const float inv1 = 1.0f / l_run1;
    #pragma unroll
    for (int onb = 0; onb < 16; onb++) {
        const int col = h * DH + onb * 8 + tig * 2;
        const size_t i0 = (size_t)row0 * (NH * DH) + col;
        const size_t i1 = (size_t)row1 * (NH * DH) + col;
        uint32_t hh_, ll_;
        split_pack(oacc[onb][0] * inv0, oacc[onb][1] * inv0, hh_, ll_);
        *(uint32_t*)(oh + i0) = hh_;
        *(uint32_t*)(ol + i0) = ll_;
        split_pack(oacc[onb][2] * inv1, oacc[onb][3] * inv1, hh_, ll_);
        *(uint32_t*)(oh + i1) = hh_;
        *(uint32_t*)(ol + i1) = ll_;
    }
}

// ---------------------------------------------------------------------------
extern "C" void kernel_launch(void* const* d_in, const int* in_sizes, int n_in,
                              void* d_out, int out_size)
{
    const int*   positions = (const int*)d_in[0];
    const float* hs = (const float*)d_in[1];
    const float* Wq = (const float*)d_in[2];
    const float* bq = (const float*)d_in[3];
    const float* Wk = (const float*)d_in[4];
    const float* bk = (const float*)d_in[5];
    const float* Wv = (const float*)d_in[6];
    const float* bv = (const float*)d_in[7];
    const float* Wo = (const float*)d_in[8];

    float* out  = (float*)d_out;
    float* kout = out + (size_t)TSEQ * HID;
    float* vout = kout + (size_t)TSEQ * NKV * DH;

    float *qbuf;
    __nv_bfloat16 *hsh, *hsl, *wqh, *wql, *wkh, *wkl, *wvh, *wvl, *woh, *wol;
    __nv_bfloat16 *qqh, *qql, *kkh, *kkl, *vvh, *vvl, *aah, *aal;
    cudaGetSymbolAddress((void**)&qbuf, g_q);
    cudaGetSymbolAddress((void**)&hsh, g_hsh);  cudaGetSymbolAddress((void**)&hsl, g_hsl);
    cudaGetSymbolAddress((void**)&wqh, g_wqh);  cudaGetSymbolAddress((void**)&wql, g_wql);
    cudaGetSymbolAddress((void**)&wkh, g_wkh);  cudaGetSymbolAddress((void**)&wkl, g_wkl);
    cudaGetSymbolAddress((void**)&wvh, g_wvh);  cudaGetSymbolAddress((void**)&wvl, g_wvl);
    cudaGetSymbolAddress((void**)&woh, g_woh);  cudaGetSymbolAddress((void**)&wol, g_wol);
    cudaGetSymbolAddress((void**)&qqh, g_qh);   cudaGetSymbolAddress((void**)&qql, g_ql);
    cudaGetSymbolAddress((void**)&kkh, g_kh);   cudaGetSymbolAddress((void**)&kkl, g_kl);
    cudaGetSymbolAddress((void**)&vvh, g_vh);   cudaGetSymbolAddress((void**)&vvl, g_vl);
    cudaGetSymbolAddress((void**)&aah, g_ah);   cudaGetSymbolAddress((void**)&aal, g_al);

    cudaFuncSetAttribute(tgemm2, cudaFuncAttributeMaxDynamicSharedMemorySize, (int)TG_SMEM);
    cudaFuncSetAttribute(attn_mma, cudaFuncAttributeMaxDynamicSharedMemorySize, (int)A2_SMEM);

    // 1. pre-split inputs (8 elems per thread)
    {
        int n4;
        n4 = TSEQ * HID / 4;
        convert_split<<<n4 / 512, 256>>>((const float4*)hs, (uint2*)hsh, (uint2*)hsl, n4);
        n4 = HID * NH * DH / 4;
        convert_split<<<n4 / 512, 256>>>((const float4*)Wq, (uint2*)wqh, (uint2*)wql, n4);
        n4 = HID * NKV * DH / 4;
        convert_split<<<n4 / 512, 256>>>((const float4*)Wk, (uint2*)wkh, (uint2*)wkl, n4);
        convert_split<<<n4 / 512, 256>>>((const float4*)Wv, (uint2*)wvh, (uint2*)wvl, n4);
        n4 = NH * DH * HID / 4;
        convert_split<<<n4 / 512, 256>>>((const float4*)Wo, (uint2*)woh, (uint2*)wol, n4);
    }

    // 2. projections (V also emits bf16 hi/lo split)
    tgemm2<<<dim3(NH * DH / 128, TSEQ / 128), 256, TG_SMEM>>>(
        hsh, hsl, wqh, wql, bq, qbuf, nullptr, nullptr, TSEQ, NH * DH, HID);
    tgemm2<<<dim3(NKV * DH / 128, TSEQ / 128), 256, TG_SMEM>>>(
        hsh, hsl, wkh, wkl, bk, kout, nullptr, nullptr, TSEQ, NKV * DH, HID);
    tgemm2<<<dim3(NKV * DH / 128, TSEQ / 128), 256, TG_SMEM>>>(
        hsh, hsl, wvh, wvl, bv, vout, vvh, vvl, TSEQ, NKV * DH, HID);

    // 3. rope
    rope_q_kernel<<<(TSEQ * NH * 64 + 255) / 256, 256>>>(positions, qbuf, qqh, qql);
    rope_k_kernel<<<(TSEQ * NKV * 64 + 255) / 256, 256>>>(positions, kout, kkh, kkl);

    // 4. attention (emits bf16 hi/lo directly)
    attn_mma<<<dim3(NH, TSEQ / 128), 256, A2_SMEM>>>(qqh, qql, kkh, kkl, vvh, vvl, aah, aal);

    // 5. O projection
    tgemm2<<<dim3(HID / 128, TSEQ / 128), 256, TG_SMEM>>>(
        aah, aal, woh, wol, nullptr, out, nullptr, nullptr, TSEQ, HID, NH * DH);
}

// round 7
// speedup vs baseline: 4.4874x; 1.4963x over previous
#include <cuda_runtime.h>
#include <cuda_fp16.h>
#include <math.h>
#include <stdint.h>

#define TSEQ 2048
#define HID  4096
#define NH   32
#define NKV  8
#define DH   128
#define GRP  (NH / NKV)

// ---------------------------------------------------------------------------
// Scratch (allocation-free rule: __device__ globals)
// ---------------------------------------------------------------------------
__device__ float g_q[(size_t)TSEQ * NH * DH];            // fp32 Q (pre-rope)
__device__ __half g_hsh[(size_t)TSEQ * HID], g_hsl[(size_t)TSEQ * HID];
__device__ __half g_wq[(size_t)HID * NH * DH];
__device__ __half g_wk[(size_t)HID * NKV * DH];
__device__ __half g_wv[(size_t)HID * NKV * DH];
__device__ __half g_wo[(size_t)NH * DH * HID];
__device__ __half g_qh[(size_t)TSEQ * NH * DH], g_ql[(size_t)TSEQ * NH * DH];
__device__ __half g_ktr[(size_t)NKV * DH * TSEQ];        // K transposed [h][d][t]
__device__ __half g_v[(size_t)TSEQ * NKV * DH];
__device__ __half g_ah[(size_t)TSEQ * NH * DH], g_al[(size_t)TSEQ * NH * DH];

// ---------------------------------------------------------------------------
// helpers
// ---------------------------------------------------------------------------
__device__ __forceinline__ uint32_t smem_u32(const void* p) {
    uint32_t a;
    asm("{ .reg .u64 t; cvta.to.shared.u64 t, %1; cvt.u32.u64 %0, t; }"
        : "=r"(a) : "l"(p));
    return a;
}
__device__ __forceinline__ uint32_t pack_f16x2(float x, float y) {
    __half2 h = __floats2half2_rn(x, y);      // x -> low half
    return *(uint32_t*)&h;
}
__device__ __forceinline__ void split_pack_f16(float x, float y,
                                               uint32_t& hi, uint32_t& lo) {
    __half2 h = __floats2half2_rn(x, y);
    float2 b = __half22float2(h);
    __half2 l = __floats2half2_rn(x - b.x, y - b.y);
    hi = *(uint32_t*)&h;
    lo = *(uint32_t*)&l;
}
__device__ __forceinline__ void ldsm4(uint32_t (&r)[4], uint32_t a) {
    asm volatile("ldmatrix.sync.aligned.m8n8.x4.shared.b16 {%0,%1,%2,%3}, [%4];"
        : "=r"(r[0]), "=r"(r[1]), "=r"(r[2]), "=r"(r[3]) : "r"(a));
}
__device__ __forceinline__ void ldsm4t(uint32_t (&r)[4], uint32_t a) {
    asm volatile("ldmatrix.sync.aligned.m8n8.x4.trans.shared.b16 {%0,%1,%2,%3}, [%4];"
        : "=r"(r[0]), "=r"(r[1]), "=r"(r[2]), "=r"(r[3]) : "r"(a));
}
__device__ __forceinline__ void mma_f16(float (&c)[4], const uint32_t (&a)[4],
                                        uint32_t b0, uint32_t b1) {
    asm volatile("mma.sync.aligned.m16n8k16.row.col.f32.f16.f16.f32 "
        "{%0,%1,%2,%3}, {%4,%5,%6,%7}, {%8,%9}, {%0,%1,%2,%3};"
        : "+f"(c[0]), "+f"(c[1]), "+f"(c[2]), "+f"(c[3])
        : "r"(a[0]), "r"(a[1]), "r"(a[2]), "r"(a[3]), "r"(b0), "r"(b1));
}
__device__ __forceinline__ void cp16(uint32_t dst, const void* src) {
    asm volatile("cp.async.cg.shared.global [%0], [%1], 16;" :: "r"(dst), "l"(src));
}
#define CP_COMMIT() asm volatile("cp.async.commit_group;" ::: "memory")
#define CP_WAIT(n)  asm volatile("cp.async.wait_group %0;" :: "n"(n) : "memory")

// ---------------------------------------------------------------------------
// fp32 -> fp16 hi + fp16 lo (residual), 8 elems/thread
// ---------------------------------------------------------------------------
__global__ void convert_split(const float4* __restrict__ in,
                              uint2* __restrict__ hi, uint2* __restrict__ lo, int n4)
{
    int i = (blockIdx.x * blockDim.x + threadIdx.x) * 2;
    if (i >= n4) return;
    float4 v0 = in[i];
    float4 v1 = in[i + 1];
    uint32_t h0, l0, h1, l1, h2, l2, h3, l3;
    split_pack_f16(v0.x, v0.y, h0, l0);
    split_pack_f16(v0.z, v0.w, h1, l1);
    split_pack_f16(v1.x, v1.y, h2, l2);
    split_pack_f16(v1.z, v1.w, h3, l3);
    hi[i]     = make_uint2(h0, h1);
    lo[i]     = make_uint2(l0, l1);
    hi[i + 1] = make_uint2(h2, h3);
    lo[i + 1] = make_uint2(l2, l3);
}

// fp32 -> fp16 plain, 8 elems/thread
__global__ void convert_h(const float4* __restrict__ in, uint4* __restrict__ out, int n8)
{
    int i = blockIdx.x * blockDim.x + threadIdx.x;
    if (i >= n8) return;
    float4 v0 = in[i * 2];
    float4 v1 = in[i * 2 + 1];
    out[i] = make_uint4(pack_f16x2(v0.x, v0.y), pack_f16x2(v0.z, v0.w),
                        pack_f16x2(v1.x, v1.y), pack_f16x2(v1.z, v1.w));
}

// ---------------------------------------------------------------------------
// Tensor-core GEMM: C = A@B (+bias). A = fp16 hi+lo (split), B = plain fp16.
// 2 MMA products: Ahi*B + Alo*B (exact up to B's fp16 rounding ~2^-12).
// CTA 128x128, K-chunk 64, 3-stage cp.async. 256 threads (4Mx2N warps).
// ---------------------------------------------------------------------------
#define TG_AT 18432u            // A tile [128][144B]
#define TG_BT 17408u            // B tile [64][272B]
#define TG_BUF (2u * TG_AT + TG_BT)         // 54272
#define TG_SMEM (3u * TG_BUF)               // 162816

__global__ __launch_bounds__(256, 1) void tgemm2(
    const __half* __restrict__ Ah, const __half* __restrict__ Al,
    const __half* __restrict__ B,
    const float* __restrict__ bias, float* __restrict__ C,
    __half* __restrict__ Ch,                // optional plain fp16 copy of C
    int M, int N, int K)
{
    extern __shared__ char sm[];
    const uint32_t sb = smem_u32(sm);

    const int tid  = threadIdx.x;
    const int wid  = tid >> 5;
    const int lane = tid & 31;
    const int bm = blockIdx.y << 7;
    const int bn = blockIdx.x << 7;
    const int wm = (wid >> 1) << 5;
    const int wn = (wid & 1) << 6;

    auto issue = [&](int k0, int buf) {
        const uint32_t base = sb + (uint32_t)buf * TG_BUF;
        #pragma unroll
        for (int i = 0; i < 4; i++) {
            int idx = tid + i * 256;
            int ar = idx >> 3, ac = idx & 7;
            const size_t aoff = (size_t)(bm + ar) * K + k0 + ac * 8;
            cp16(base + (uint32_t)(ar * 144 + ac * 16), Ah + aoff);
            cp16(base + TG_AT + (uint32_t)(ar * 144 + ac * 16), Al + aoff);
            int br = idx >> 4, bc = idx & 15;
            const size_t boff = (size_t)(k0 + br) * N + bn + bc * 8;
            cp16(base + 2u * TG_AT + (uint32_t)(br * 272 + bc * 16), B + boff);
        }
    };

    float acc[2][8][4];
    #pragma unroll
    for (int mi = 0; mi < 2; mi++)
        #pragma unroll
        for (int j = 0; j < 8; j++)
            #pragma unroll
            for (int q = 0; q < 4; q++) acc[mi][j][q] = 0.f;

    const int NC = K >> 6;
    issue(0, 0); CP_COMMIT();
    if (NC > 1) { issue(64, 1); CP_COMMIT(); }

    for (int c = 0; c < NC; c++) {
        if (c + 1 < NC) { CP_WAIT(1); } else { CP_WAIT(0); }
        __syncthreads();
        if (c + 2 < NC) { issue((c + 2) << 6, (c + 2) % 3); CP_COMMIT(); }

        const uint32_t base = sb + (uint32_t)(c % 3) * TG_BUF;
        #pragma unroll
        for (int ks = 0; ks < 4; ks++) {
            uint32_t afh[2][4], afl[2][4];
            #pragma unroll
            for (int mi = 0; mi < 2; mi++) {
                uint32_t ro = base + (uint32_t)((wm + mi * 16 + (lane & 15)) * 144
                                                + ks * 32 + (lane >> 4) * 16);
                ldsm4(afh[mi], ro);
                ldsm4(afl[mi], ro + TG_AT);
            }
            uint32_t bf[4][4];
            const uint32_t kro = base + 2u * TG_AT
                + (uint32_t)((ks * 16 + (lane & 15)) * 272 + (lane >> 4) * 16);
            #pragma unroll
            for (int nb = 0; nb < 4; nb++)
                ldsm4t(bf[nb], kro + (uint32_t)((wn + nb * 16) * 2));
            #pragma unroll
            for (int mi = 0; mi < 2; mi++)
                #pragma unroll
                for (int nb = 0; nb < 4; nb++)
                    #pragma unroll
                    for (int hh = 0; hh < 2; hh++) {
                        float (&cc)[4] = acc[mi][nb * 2 + hh];
                        mma_f16(cc, afh[mi], bf[nb][2 * hh], bf[nb][2 * hh + 1]);
                        mma_f16(cc, afl[mi], bf[nb][2 * hh], bf[nb][2 * hh + 1]);
                    }
        }
    }

    // epilogue
    const int r0 = lane >> 2;
    const int c0 = (lane & 3) << 1;
    #pragma unroll
    for (int mi = 0; mi < 2; mi++) {
        #pragma unroll
        for (int j = 0; j < 8; j++) {
            const int col = bn + wn + j * 8 + c0;
            float bias0 = 0.f, bias1 = 0.f;
            if (bias != nullptr) { bias0 = bias[col]; bias1 = bias[col + 1]; }
            const int row_a = bm + wm + mi * 16 + r0;
            const int row_b = row_a + 8;
            float va0 = acc[mi][j][0] + bias0, va1 = acc[mi][j][1] + bias1;
            float vb0 = acc[mi][j][2] + bias0, vb1 = acc[mi][j][3] + bias1;
            float* Ca = C + (size_t)row_a * N + col;
            float* Cb = C + (size_t)row_b * N + col;
            Ca[0] = va0; Ca[1] = va1;
            Cb[0] = vb0; Cb[1] = vb1;
            if (Ch != nullptr) {
                *(uint32_t*)(Ch + (size_t)row_a * N + col) = pack_f16x2(va0, va1);
                *(uint32_t*)(Ch + (size_t)row_b * N + col) = pack_f16x2(vb0, vb1);
            }
        }
    }
}

// ---------------------------------------------------------------------------
// RoPE Q: fp32 pre-rope Q -> fp16 hi/lo roped Q, pre-scaled by 1/sqrt(D).
// ---------------------------------------------------------------------------
__global__ void rope_q_kernel(const int* __restrict__ positions,
                              const float* __restrict__ x,
                              __half* __restrict__ xh, __half* __restrict__ xl)
{
    int i = blockIdx.x * blockDim.x + threadIdx.x;
    if (i >= TSEQ * NH * 64) return;
    int d = i & 63;
    int rest = i >> 6;
    int hh = rest % NH;
    int t  = rest / NH;

    const float scale = 0.08838834764831843f;
    float pos = (float)positions[t];
    float inv_freq = powf(1.0e6f, -(float)d * (1.0f / 64.0f));
    float s, c;
    sincosf(pos * inv_freq, &s, &c);

    size_t base = (size_t)t * (NH * DH) + (size_t)hh * DH;
    float x1 = x[base + d];
    float x2 = x[base + d + 64];
    float y1 = (x1 * c - x2 * s) * scale;
    float y2 = (x2 * c + x1 * s) * scale;
    __half h1 = __float2half_rn(y1);
    __half h2 = __float2half_rn(y2);
    xh[base + d]      = h1;
    xl[base + d]      = __float2half_rn(y1 - __half2float(h1));
    xh[base + d + 64] = h2;
    xl[base + d + 64] = __float2half_rn(y2 - __half2float(h2));
}

// ---------------------------------------------------------------------------
// RoPE K: in-place fp32 (kv_fused output) + transposed plain fp16 ktr[h][d][t].
// ---------------------------------------------------------------------------
__global__ void rope_k_kernel(const int* __restrict__ positions,
                              float* __restrict__ x, __half* __restrict__ ktr)
{
    int i = blockIdx.x * blockDim.x + threadIdx.x;
    if (i >= TSEQ * NKV * 64) return;
    int d = i & 63;
    int rest = i >> 6;
    int hh = rest % NKV;
    int t  = rest / NKV;

    float pos = (float)positions[t];
    float inv_freq = powf(1.0e6f, -(float)d * (1.0f / 64.0f));
    float s, c;
    sincosf(pos * inv_freq, &s, &c);

    size_t base = (size_t)t * (NKV * DH) + (size_t)hh * DH;
    float x1 = x[base + d];
    float x2 = x[base + d + 64];
    float y1 = x1 * c - x2 * s;
    float y2 = x2 * c + x1 * s;
    x[base + d]      = y1;
    x[base + d + 64] = y2;
    ktr[((size_t)hh * DH + d) * TSEQ + t]      = __float2half_rn(y1);
    ktr[((size_t)hh * DH + d + 64) * TSEQ + t] = __float2half_rn(y2);
}

// ---------------------------------------------------------------------------
// MMA flash attention: 128 q-rows/CTA, 256 threads. Q fp16 hi/lo (pre-scaled),
// K/V plain fp16 (K pre-transposed in gmem), P split x2. cp.async 2-stage KV.
// Grid (NH, T/128); m0 reversed for wave balance.
// ---------------------------------------------------------------------------
#define A2_Q  34816u    // [128][272B]
#define A2_KT 18432u    // [128][144B]
#define A2_V  17408u    // [64][272B]
#define O_QH 0u
#define O_QL A2_Q
#define O_KV0 (2u * A2_Q)
#define KV_BUF (A2_KT + A2_V)
#define A2_SMEM (2u * A2_Q + 2u * KV_BUF)   // 141312

__global__ __launch_bounds__(256, 1) void attn_mma(
    const __half* __restrict__ qh, const __half* __restrict__ ql,
    const __half* __restrict__ ktr, const __half* __restrict__ v,
    __half* __restrict__ oh, __half* __restrict__ ol)
{
    extern __shared__ char sm[];
    const uint32_t sb = smem_u32(sm);
    const int h  = blockIdx.x;
    const int m0 = (int)(gridDim.y - 1 - blockIdx.y) << 7;
    const int kvh = h / GRP;
    const int tid = threadIdx.x;
    const int wid = tid >> 5;
    const int lane = tid & 31;
    const int wm = wid << 4;
    const int gID = lane >> 2;
    const int tig = lane & 3;

    const __half* ktr_h = ktr + (size_t)kvh * DH * TSEQ;

    auto issue_kv = [&](int n0, int b) {
        const uint32_t kb = sb + O_KV0 + (uint32_t)b * KV_BUF;
        #pragma unroll
        for (int i = 0; i < 4; i++) {
            int idx = tid + i * 256;
            int dr = idx >> 3, dc = idx & 7;      // KT: 128 rows x 8 chunks
            cp16(kb + (uint32_t)(dr * 144 + dc * 16),
                 ktr_h + (size_t)dr * TSEQ + n0 + dc * 8);
            int vr = idx >> 4, vc = idx & 15;     // V: 64 rows x 16 chunks
            cp16(kb + A2_KT + (uint32_t)(vr * 272 + vc * 16),
                 v + (size_t)(n0 + vr) * (NKV * DH) + (size_t)kvh * DH + vc * 8);
        }
    };

    // load Q tile (128 x 128) hi/lo
    #pragma unroll
    for (int i = 0; i < 8; i++) {
        int idx = tid + i * 256;
        int r = idx >> 4, ch = idx & 15;
        const size_t go = (size_t)(m0 + r) * (NH * DH) + (size_t)h * DH + ch * 8;
        *(uint4*)(sm + O_QH + r * 272 + ch * 16) = *(const uint4*)(qh + go);
        *(uint4*)(sm + O_QL + r * 272 + ch * 16) = *(const uint4*)(ql + go);
    }

    float oacc[16][4];
    #pragma unroll
    for (int j = 0; j < 16; j++)
        #pragma unroll
        for (int q = 0; q < 4; q++) oacc[j][q] = 0.f;
    float m_run0 = -1e30f, m_run1 = -1e30f, l_run0 = 0.f, l_run1 = 0.f;

    const int row0 = m0 + wm + gID;
    const int row1 = row0 + 8;
    const int warp_max_row = m0 + wm + 15;

    const int nblocks = (m0 >> 6) + 2;
    issue_kv(0, 0); CP_COMMIT();

    for (int blk = 0; blk < nblocks; blk++) {
        const int n0 = blk << 6;
        const bool more = (blk + 1 < nblocks);
        if (more) { issue_kv((blk + 1) << 6, (blk + 1) & 1); CP_COMMIT(); CP_WAIT(1); }
        else      { CP_WAIT(0); }
        __syncthreads();

        if (n0 <= warp_max_row) {
            const uint32_t kb = sb + O_KV0 + (uint32_t)(blk & 1) * KV_BUF;

            // ---- S = Q K^T (2 products) ----
            float sacc[8][4];
            #pragma unroll
            for (int j = 0; j < 8; j++)
                #pragma unroll
                for (int q = 0; q < 4; q++) sacc[j][q] = 0.f;

            #pragma unroll
            for (int ks = 0; ks < 8; ks++) {
                uint32_t aH[4], aL[4];
                uint32_t ro = sb + O_QH + (uint32_t)((wm + (lane & 15)) * 272
                                                     + ks * 32 + (lane >> 4) * 16);
                ldsm4(aH, ro);
                ldsm4(aL, ro + A2_Q);
                const uint32_t kro = kb
                    + (uint32_t)((ks * 16 + (lane & 15)) * 144 + (lane >> 4) * 16);
                #pragma unroll
                for (int nb = 0; nb < 4; nb++) {
                    uint32_t bk4[4];
                    ldsm4t(bk4, kro + (uint32_t)(nb * 32));
                    #pragma unroll
                    for (int hh = 0; hh < 2; hh++) {
                        float (&cc)[4] = sacc[nb * 2 + hh];
                        mma_f16(cc, aH, bk4[2 * hh], bk4[2 * hh + 1]);
                        mma_f16(cc, aL, bk4[2 * hh], bk4[2 * hh + 1]);
                    }
                }
            }

            // ---- online softmax ----
            float mx0 = -1e30f, mx1 = -1e30f;
            #pragma unroll
            for (int nb = 0; nb < 8; nb++) {
                #pragma unroll
                for (int j = 0; j < 2; j++) {
                    const int col = n0 + nb * 8 + tig * 2 + j;
                    float s0 = sacc[nb][j];
                    float s1 = sacc[nb][2 + j];
                    if (col > row0) s0 = -1e30f;
                    if (col > row1) s1 = -1e30f;
                    sacc[nb][j] = s0;
                    sacc[nb][2 + j] = s1;
                    mx0 = fmaxf(mx0, s0);
                    mx1 = fmaxf(mx1, s1);
                }
            }
            #pragma unroll
            for (int off = 1; off <= 2; off <<= 1) {
                mx0 = fmaxf(mx0, __shfl_xor_sync(0xffffffffu, mx0, off));
                mx1 = fmaxf(mx1, __shfl_xor_sync(0xffffffffu, mx1, off));
            }
            float mn0 = fmaxf(m_run0, mx0);
            float mn1 = fmaxf(m_run1, mx1);
            float cf0 = __expf(m_run0 - mn0);
            float cf1 = __expf(m_run1 - mn1);
            m_run0 = mn0; m_run1 = mn1;
            float su0 = 0.f, su1 = 0.f;
            #pragma unroll
            for (int nb = 0; nb < 8; nb++) {
                #pragma unroll
                for (int j = 0; j < 2; j++) {
                    float p0 = __expf(sacc[nb][j] - mn0);
                    float p1 = __expf(sacc[nb][2 + j] - mn1);
                    sacc[nb][j] = p0;
                    sacc[nb][2 + j] = p1;
                    su0 += p0;
                    su1 += p1;
                }
            }
            #pragma unroll
            for (int off = 1; off <= 2; off <<= 1) {
                su0 += __shfl_xor_sync(0xffffffffu, su0, off);
                su1 += __shfl_xor_sync(0xffffffffu, su1, off);
            }
            l_run0 = l_run0 * cf0 + su0;
            l_run1 = l_run1 * cf1 + su1;
            #pragma unroll
            for (int j = 0; j < 16; j++) {
                oacc[j][0] *= cf0;
                oacc[j][1] *= cf0;
                oacc[j][2] *= cf1;
                oacc[j][3] *= cf1;
            }

            // ---- O += P V (2 products; P split register-direct) ----
            #pragma unroll
            for (int ks = 0; ks < 4; ks++) {
                uint32_t ph[4], pl[4];
                split_pack_f16(sacc[2 * ks][0],     sacc[2 * ks][1],     ph[0], pl[0]);
                split_pack_f16(sacc[2 * ks][2],     sacc[2 * ks][3],     ph[1], pl[1]);
                split_pack_f16(sacc[2 * ks + 1][0], sacc[2 * ks + 1][1], ph[2], pl[2]);
                split_pack_f16(sacc[2 * ks + 1][2], sacc[2 * ks + 1][3], ph[3], pl[3]);
                const uint32_t vro = kb + A2_KT
                    + (uint32_t)((ks * 16 + (lane & 15)) * 272 + (lane >> 4) * 16);
                #pragma unroll
                for (int nbv = 0; nbv < 8; nbv++) {
                    uint32_t vb4[4];
                    ldsm4t(vb4, vro + (uint32_t)(nbv * 32));
                    #pragma unroll
                    for (int hh = 0; hh < 2; hh++) {
                        float (&cc)[4] = oacc[nbv * 2 + hh];
                        mma_f16(cc, ph, vb4[2 * hh], vb4[2 * hh + 1]);
                        mma_f16(cc, pl, vb4[2 * hh], vb4[2 * hh + 1]);
                    }
                }
            }
        }
        __syncthreads();
    }

    // epilogue: write fp16 hi/lo split of normalized output
    const float inv0 = 1.0f / l_run0;
    const float inv1 = 1.0f / l_run1;
    #pragma unroll
    for (int onb = 0; onb < 16; onb++) {
        const int col = h * DH + onb * 8 + tig * 2;
        const size_t i0 = (size_t)row0 * (NH * DH) + col;
        const size_t i1 = (size_t)row1 * (NH * DH) + col;
        uint32_t hh_, ll_;
        split_pack_f16(oacc[onb][0] * inv0, oacc[onb][1] * inv0, hh_, ll_);
        *(uint32_t*)(oh + i0) = hh_;
        *(uint32_t*)(ol + i0) = ll_;
        split_pack_f16(oacc[onb][2] * inv1, oacc[onb][3] * inv1, hh_, ll_);
        *(uint32_t*)(oh + i1) = hh_;
        *(uint32_t*)(ol + i1) = ll_;
    }
}

// ---------------------------------------------------------------------------
extern "C" void kernel_launch(void* const* d_in, const int* in_sizes, int n_in,
                              void* d_out, int out_size)
{
    const int*   positions = (const int*)d_in[0];
    const float* hs = (const float*)d_in[1];
    const float* Wq = (const float*)d_in[2];
    const float* bq = (const float*)d_in[3];
    const float* Wk = (const float*)d_in[4];
    const float* bk = (const float*)d_in[5];
    const float* Wv = (const float*)d_in[6];
    const float* bv = (const float*)d_in[7];
    const float* Wo = (const float*)d_in[8];

    float* out  = (float*)d_out;
    float* kout = out + (size_t)TSEQ * HID;
    float* vout = kout + (size_t)TSEQ * NKV * DH;

    float *qbuf;
    __half *hsh, *hsl, *wq, *wk, *wv, *wo, *qqh, *qql, *ktr, *vv, *aah, *aal;
    cudaGetSymbolAddress((void**)&qbuf, g_q);
    cudaGetSymbolAddress((void**)&hsh, g_hsh);  cudaGetSymbolAddress((void**)&hsl, g_hsl);
    cudaGetSymbolAddress((void**)&wq, g_wq);    cudaGetSymbolAddress((void**)&wk, g_wk);
    cudaGetSymbolAddress((void**)&wv, g_wv);    cudaGetSymbolAddress((void**)&wo, g_wo);
    cudaGetSymbolAddress((void**)&qqh, g_qh);   cudaGetSymbolAddress((void**)&qql, g_ql);
    cudaGetSymbolAddress((void**)&ktr, g_ktr);  cudaGetSymbolAddress((void**)&vv, g_v);
    cudaGetSymbolAddress((void**)&aah, g_ah);   cudaGetSymbolAddress((void**)&aal, g_al);

    cudaFuncSetAttribute(tgemm2, cudaFuncAttributeMaxDynamicSharedMemorySize, (int)TG_SMEM);
    cudaFuncSetAttribute(attn_mma, cudaFuncAttributeMaxDynamicSharedMemorySize, (int)A2_SMEM);

    // 1. converts: hs -> fp16 hi/lo split; weights -> plain fp16
    {
        int n4 = TSEQ * HID / 4;
        convert_split<<<n4 / 512, 256>>>((const float4*)hs, (uint2*)hsh, (uint2*)hsl, n4);
        int n8;
        n8 = HID * NH * DH / 8;
        convert_h<<<n8 / 256, 256>>>((const float4*)Wq, (uint4*)wq, n8);
        n8 = HID * NKV * DH / 8;
        convert_h<<<n8 / 256, 256>>>((const float4*)Wk, (uint4*)wk, n8);
        convert_h<<<n8 / 256, 256>>>((const float4*)Wv, (uint4*)wv, n8);
        n8 = NH * DH * HID / 8;
        convert_h<<<n8 / 256, 256>>>((const float4*)Wo, (uint4*)wo, n8);
    }

    // 2. projections
    tgemm2<<<dim3(NH * DH / 128, TSEQ / 128), 256, TG_SMEM>>>(
        hsh, hsl, wq, bq, qbuf, nullptr, TSEQ, NH * DH, HID);
    tgemm2<<<dim3(NKV * DH / 128, TSEQ / 128), 256, TG_SMEM>>>(
        hsh, hsl, wk, bk, kout, nullptr, TSEQ, NKV * DH, HID);
    tgemm2<<<dim3(NKV * DH / 128, TSEQ / 128), 256, TG_SMEM>>>(
        hsh, hsl, wv, bv, vout, vv, TSEQ, NKV * DH, HID);

    // 3. rope
    rope_q_kernel<<<(TSEQ * NH * 64 + 255) / 256, 256>>>(positions, qbuf, qqh, qql);
    rope_k_kernel<<<(TSEQ * NKV * 64 + 255) / 256, 256>>>(positions, kout, ktr);

    // 4. attention
    attn_mma<<<dim3(NH, TSEQ / 128), 256, A2_SMEM>>>(qqh, qql, ktr, vv, aah, aal);

    // 5. O projection
    tgemm2<<<dim3(HID / 128, TSEQ / 128), 256, TG_SMEM>>>(
        aah, aal, wo, nullptr, out, nullptr, TSEQ, HID, NH * DH);
}

// round 9
// speedup vs baseline: 5.1199x; 1.1409x over previous
#include <cuda_runtime.h>
#include <cuda_fp16.h>
#include <math.h>
#include <stdint.h>

#define TSEQ 2048
#define HID  4096
#define NH   32
#define NKV  8
#define DH   128
#define GRP  (NH / NKV)

// ---------------------------------------------------------------------------
// Scratch (allocation-free rule: __device__ globals)
// ---------------------------------------------------------------------------
__device__ float g_q[(size_t)TSEQ * NH * DH];            // fp32 Q (pre-rope)
__device__ float2 g_tab[(size_t)TSEQ * 64];              // rope (cos,sin)
__device__ __half g_hsh[(size_t)TSEQ * HID], g_hsl[(size_t)TSEQ * HID];
__device__ __half g_wq[(size_t)HID * NH * DH];
__device__ __half g_wk[(size_t)HID * NKV * DH];
__device__ __half g_wv[(size_t)HID * NKV * DH];
__device__ __half g_wo[(size_t)NH * DH * HID];
__device__ __half g_qh[(size_t)TSEQ * NH * DH], g_ql[(size_t)TSEQ * NH * DH];
__device__ __half g_ktr[(size_t)NKV * DH * TSEQ];        // K transposed [h][d][t]
__device__ __half g_v[(size_t)TSEQ * NKV * DH];
__device__ __half g_ah[(size_t)TSEQ * NH * DH], g_al[(size_t)TSEQ * NH * DH];

// ---------------------------------------------------------------------------
// helpers
// ---------------------------------------------------------------------------
__device__ __forceinline__ uint32_t smem_u32(const void* p) {
    uint32_t a;
    asm("{ .reg .u64 t; cvta.to.shared.u64 t, %1; cvt.u32.u64 %0, t; }"
        : "=r"(a) : "l"(p));
    return a;
}
__device__ __forceinline__ uint32_t pack_f16x2(float x, float y) {
    __half2 h = __floats2half2_rn(x, y);
    return *(uint32_t*)&h;
}
__device__ __forceinline__ void split_pack_f16(float x, float y,
                                               uint32_t& hi, uint32_t& lo) {
    __half2 h = __floats2half2_rn(x, y);
    float2 b = __half22float2(h);
    __half2 l = __floats2half2_rn(x - b.x, y - b.y);
    hi = *(uint32_t*)&h;
    lo = *(uint32_t*)&l;
}
__device__ __forceinline__ void ldsm4(uint32_t (&r)[4], uint32_t a) {
    asm volatile("ldmatrix.sync.aligned.m8n8.x4.shared.b16 {%0,%1,%2,%3}, [%4];"
        : "=r"(r[0]), "=r"(r[1]), "=r"(r[2]), "=r"(r[3]) : "r"(a));
}
__device__ __forceinline__ void ldsm4t(uint32_t (&r)[4], uint32_t a) {
    asm volatile("ldmatrix.sync.aligned.m8n8.x4.trans.shared.b16 {%0,%1,%2,%3}, [%4];"
        : "=r"(r[0]), "=r"(r[1]), "=r"(r[2]), "=r"(r[3]) : "r"(a));
}
__device__ __forceinline__ void mma_f16(float (&c)[4], const uint32_t (&a)[4],
                                        uint32_t b0, uint32_t b1) {
    asm volatile("mma.sync.aligned.m16n8k16.row.col.f32.f16.f16.f32 "
        "{%0,%1,%2,%3}, {%4,%5,%6,%7}, {%8,%9}, {%0,%1,%2,%3};"
        : "+f"(c[0]), "+f"(c[1]), "+f"(c[2]), "+f"(c[3])
        : "r"(a[0]), "r"(a[1]), "r"(a[2]), "r"(a[3]), "r"(b0), "r"(b1));
}
__device__ __forceinline__ void cp16(uint32_t dst, const void* src) {
    asm volatile("cp.async.cg.shared.global [%0], [%1], 16;" :: "r"(dst), "l"(src));
}
#define CP_COMMIT() asm volatile("cp.async.commit_group;" ::: "memory")
#define CP_WAIT(n)  asm volatile("cp.async.wait_group %0;" :: "n"(n) : "memory")

// ---------------------------------------------------------------------------
// converts
// ---------------------------------------------------------------------------
__global__ void convert_split(const float4* __restrict__ in,
                              uint2* __restrict__ hi, uint2* __restrict__ lo, int n4)
{
    int i = (blockIdx.x * blockDim.x + threadIdx.x) * 2;
    if (i >= n4) return;
    float4 v0 = in[i];
    float4 v1 = in[i + 1];
    uint32_t h0, l0, h1, l1, h2, l2, h3, l3;
    split_pack_f16(v0.x, v0.y, h0, l0);
    split_pack_f16(v0.z, v0.w, h1, l1);
    split_pack_f16(v1.x, v1.y, h2, l2);
    split_pack_f16(v1.z, v1.w, h3, l3);
    hi[i]     = make_uint2(h0, h1);
    lo[i]     = make_uint2(l0, l1);
    hi[i + 1] = make_uint2(h2, h3);
    lo[i + 1] = make_uint2(l2, l3);
}

// Fused fp32->fp16 convert for all 4 weight matrices (8 elems/thread).
#define WQ_N8 ((HID * NH * DH) / 8)
#define WK_N8 ((HID * NKV * DH) / 8)
#define WV_N8 ((HID * NKV * DH) / 8)
#define WO_N8 ((NH * DH * HID) / 8)
#define W_TOT8 (WQ_N8 + WK_N8 + WV_N8 + WO_N8)
__global__ void convert_weights(const float4* __restrict__ wq,
                                const float4* __restrict__ wk,
                                const float4* __restrict__ wv,
                                const float4* __restrict__ wo)
{
    int i = blockIdx.x * blockDim.x + threadIdx.x;
    if (i >= W_TOT8) return;
    const float4* src;
    uint4* dst;
    int j = i;
    if (j < WQ_N8)                { src = wq; dst = (uint4*)g_wq; }
    else if ((j -= WQ_N8) < WK_N8){ src = wk; dst = (uint4*)g_wk; }
    else if ((j -= WK_N8) < WV_N8){ src = wv; dst = (uint4*)g_wv; }
    else { j -= WV_N8;              src = wo; dst = (uint4*)g_wo; }
    float4 v0 = src[j * 2];
    float4 v1 = src[j * 2 + 1];
    dst[j] = make_uint4(pack_f16x2(v0.x, v0.y), pack_f16x2(v0.z, v0.w),
                        pack_f16x2(v1.x, v1.y), pack_f16x2(v1.z, v1.w));
}

// ---------------------------------------------------------------------------
// Core GEMM tile: C[bm:+128, bn:+128] = A@B (+bias). A fp16 hi/lo split,
// B plain fp16. 2-stage cp.async, 256 threads (4Mx2N warps), 2 CTAs/SM.
// ---------------------------------------------------------------------------
#define TG_AT 18432u            // A tile [128][144B]
#define TG_BT 17408u            // B tile [64][272B]
#define TG_BUF (2u * TG_AT + TG_BT)         // 54272
#define TG_SMEM (2u * TG_BUF)               // 108544

__device__ __forceinline__ void gemm_tile(
    const __half* __restrict__ Ah, const __half* __restrict__ Al,
    const __half* __restrict__ B,
    const float* __restrict__ bias, float* __restrict__ C,
    __half* __restrict__ Ch,
    int N, int K, int bm, int bn, char* sm)
{
    const uint32_t sb = smem_u32(sm);
    const int tid  = threadIdx.x;
    const int wid  = tid >> 5;
    const int lane = tid & 31;
    const int wm = (wid >> 1) << 5;
    const int wn = (wid & 1) << 6;

    auto issue = [&](int k0, int buf) {
        const uint32_t base = sb + (uint32_t)buf * TG_BUF;
        #pragma unroll
        for (int i = 0; i < 4; i++) {
            int idx = tid + i * 256;
            int ar = idx >> 3, ac = idx & 7;
            const size_t aoff = (size_t)(bm + ar) * K + k0 + ac * 8;
            cp16(base + (uint32_t)(ar * 144 + ac * 16), Ah + aoff);
            cp16(base + TG_AT + (uint32_t)(ar * 144 + ac * 16), Al + aoff);
            int br = idx >> 4, bc = idx & 15;
            const size_t boff = (size_t)(k0 + br) * N + bn + bc * 8;
            cp16(base + 2u * TG_AT + (uint32_t)(br * 272 + bc * 16), B + boff);
        }
    };

    float acc[2][8][4];
    #pragma unroll
    for (int mi = 0; mi < 2; mi++)
        #pragma unroll
        for (int j = 0; j < 8; j++)
            #pragma unroll
            for (int q = 0; q < 4; q++) acc[mi][j][q] = 0.f;

    const int NC = K >> 6;
    issue(0, 0); CP_COMMIT();

    for (int c = 0; c < NC; c++) {
        if (c + 1 < NC) { issue((c + 1) << 6, (c + 1) & 1); CP_COMMIT(); CP_WAIT(1); }
        else            { CP_WAIT(0); }
        __syncthreads();

        const uint32_t base = sb + (uint32_t)(c & 1) * TG_BUF;
        #pragma unroll
        for (int ks = 0; ks < 4; ks++) {
            uint32_t afh[2][4], afl[2][4];
            #pragma unroll
            for (int mi = 0; mi < 2; mi++) {
                uint32_t ro = base + (uint32_t)((wm + mi * 16 + (lane & 15)) * 144
                                                + ks * 32 + (lane >> 4) * 16);
                ldsm4(afh[mi], ro);
                ldsm4(afl[mi], ro + TG_AT);
            }
            uint32_t bf[4][4];
            const uint32_t kro = base + 2u * TG_AT
                + (uint32_t)((ks * 16 + (lane & 15)) * 272 + (lane >> 4) * 16);
            #pragma unroll
            for (int nb = 0; nb < 4; nb++)
                ldsm4t(bf[nb], kro + (uint32_t)((wn + nb * 16) * 2));
            #pragma unroll
            for (int mi = 0; mi < 2; mi++)
                #pragma unroll
                for (int nb = 0; nb < 4; nb++)
                    #pragma unroll
                    for (int hh = 0; hh < 2; hh++) {
                        float (&cc)[4] = acc[mi][nb * 2 + hh];
                        mma_f16(cc, afh[mi], bf[nb][2 * hh], bf[nb][2 * hh + 1]);
                        mma_f16(cc, afl[mi], bf[nb][2 * hh], bf[nb][2 * hh + 1]);
                    }
        }
        __syncthreads();   // all warps done with this buffer before re-fill
    }

    // epilogue
    const int r0 = lane >> 2;
    const int c0 = (lane & 3) << 1;
    #pragma unroll
    for (int mi = 0; mi < 2; mi++) {
        #pragma unroll
        for (int j = 0; j < 8; j++) {
            const int col = bn + wn + j * 8 + c0;
            float bias0 = 0.f, bias1 = 0.f;
            if (bias != nullptr) { bias0 = bias[col]; bias1 = bias[col + 1]; }
            const int row_a = bm + wm + mi * 16 + r0;
            const int row_b = row_a + 8;
            float va0 = acc[mi][j][0] + bias0, va1 = acc[mi][j][1] + bias1;
            float vb0 = acc[mi][j][2] + bias0, vb1 = acc[mi][j][3] + bias1;
            float* Ca = C + (size_t)row_a * N + col;
            float* Cb = C + (size_t)row_b * N + col;
            Ca[0] = va0; Ca[1] = va1;
            Cb[0] = vb0; Cb[1] = vb1;
            if (Ch != nullptr) {
                *(uint32_t*)(Ch + (size_t)row_a * N + col) = pack_f16x2(va0, va1);
                *(uint32_t*)(Ch + (size_t)row_b * N + col) = pack_f16x2(vb0, vb1);
            }
        }
    }
}

// Fused QKV projection: grid (48, 16). bx<32 -> Q, [32,40) -> K, [40,48) -> V.
__global__ __launch_bounds__(256, 2) void tgemm_qkv(
    const float* __restrict__ bq, const float* __restrict__ bk,
    const float* __restrict__ bv,
    float* __restrict__ qbuf, float* __restrict__ kout, float* __restrict__ vout)
{
    extern __shared__ char sm[];
    const int bx = blockIdx.x;
    const int bm = blockIdx.y << 7;
    if (bx < 32) {
        gemm_tile(g_hsh, g_hsl, g_wq, bq, qbuf, nullptr,
                  NH * DH, HID, bm, bx << 7, sm);
    } else if (bx < 40) {
        gemm_tile(g_hsh, g_hsl, g_wk, bk, kout, nullptr,
                  NKV * DH, HID, bm, (bx - 32) << 7, sm);
    } else {
        gemm_tile(g_hsh, g_hsl, g_wv, bv, vout, g_v,
                  NKV * DH, HID, bm, (bx - 40) << 7, sm);
    }
}

// O projection: grid (32, 16).
__global__ __launch_bounds__(256, 2) void tgemm_o(float* __restrict__ out)
{
    extern __shared__ char sm[];
    gemm_tile(g_ah, g_al, g_wo, nullptr, out, nullptr,
              HID, NH * DH, blockIdx.y << 7, blockIdx.x << 7, sm);
}

// ---------------------------------------------------------------------------
// rope table + rope kernels
// ---------------------------------------------------------------------------
__global__ void rope_tab_kernel(const int* __restrict__ positions)
{
    int i = blockIdx.x * blockDim.x + threadIdx.x;
    if (i >= TSEQ * 64) return;
    int d = i & 63, t = i >> 6;
    float pos = (float)positions[t];
    float inv_freq = powf(1.0e6f, -(float)d * (1.0f / 64.0f));
    float s, c;
    sincosf(pos * inv_freq, &s, &c);
    g_tab[i] = make_float2(c, s);
}

__global__ void rope_q_kernel(const float* __restrict__ x,
                              __half* __restrict__ xh, __half* __restrict__ xl)
{
    int i = blockIdx.x * blockDim.x + threadIdx.x;
    if (i >= TSEQ * NH * 64) return;
    int d = i & 63;
    int rest = i >> 6;
    int hh = rest % NH;
    int t  = rest / NH;

    const float scale = 0.08838834764831843f;
    float2 cs = g_tab[t * 64 + d];

    size_t base = (size_t)t * (NH * DH) + (size_t)hh * DH;
    float x1 = x[base + d];
    float x2 = x[base + d + 64];
    float y1 = (x1 * cs.x - x2 * cs.y) * scale;
    float y2 = (x2 * cs.x + x1 * cs.y) * scale;
    __half h1 = __float2half_rn(y1);
    __half h2 = __float2half_rn(y2);
    xh[base + d]      = h1;
    xl[base + d]      = __float2half_rn(y1 - __half2float(h1));
    xh[base + d + 64] = h2;
    xl[base + d + 64] = __float2half_rn(y2 - __half2float(h2));
}

__global__ void rope_k_kernel(float* __restrict__ x)
{
    int i = blockIdx.x * blockDim.x + threadIdx.x;
    if (i >= TSEQ * NKV * 64) return;
    int d = i & 63;
    int rest = i >> 6;
    int hh = rest % NKV;
    int t  = rest / NKV;

    float2 cs = g_tab[t * 64 + d];
    size_t base = (size_t)t * (NKV * DH) + (size_t)hh * DH;
    float x1 = x[base + d];
    float x2 = x[base + d + 64];
    float y1 = x1 * cs.x - x2 * cs.y;
    float y2 = x2 * cs.x + x1 * cs.y;
    x[base + d]      = y1;
    x[base + d + 64] = y2;
    g_ktr[((size_t)hh * DH + d) * TSEQ + t]      = __float2half_rn(y1);
    g_ktr[((size_t)hh * DH + d + 64) * TSEQ + t] = __float2half_rn(y2);
}

// ---------------------------------------------------------------------------
// MMA flash attention: 128 q-rows/CTA, 256 threads. Q fp16 hi/lo (pre-scaled),
// K/V plain fp16 (K pre-transposed), P split x2. cp.async 2-stage KV.
// Grid (NH, T/128); m0 reversed for wave balance.
// ---------------------------------------------------------------------------
#define A2_Q  34816u    // [128][272B]
#define A2_KT 18432u    // [128][144B]
#define A2_V  17408u    // [64][272B]
#define O_QH 0u
#define O_QL A2_Q
#define O_KV0 (2u * A2_Q)
#define KV_BUF (A2_KT + A2_V)
#define A2_SMEM (2u * A2_Q + 2u * KV_BUF)   // 141312

__global__ __launch_bounds__(256, 1) void attn_mma(
    __half* __restrict__ oh, __half* __restrict__ ol)
{
    extern __shared__ char sm[];
    const uint32_t sb = smem_u32(sm);
    const int h  = blockIdx.x;
    const int m0 = (int)(gridDim.y - 1 - blockIdx.y) << 7;
    const int kvh = h / GRP;
    const int tid = threadIdx.x;
    const int wid = tid >> 5;
    const int lane = tid & 31;
    const int wm = wid << 4;
    const int gID = lane >> 2;
    const int tig = lane & 3;

    const __half* ktr_h = g_ktr + (size_t)kvh * DH * TSEQ;

    auto issue_kv = [&](int n0, int b) {
        const uint32_t kb = sb + O_KV0 + (uint32_t)b * KV_BUF;
        #pragma unroll
        for (int i = 0; i < 4; i++) {
            int idx = tid + i * 256;
            int dr = idx >> 3, dc = idx & 7;
            cp16(kb + (uint32_t)(dr * 144 + dc * 16),
                 ktr_h + (size_t)dr * TSEQ + n0 + dc * 8);
            int vr = idx >> 4, vc = idx & 15;
            cp16(kb + A2_KT + (uint32_t)(vr * 272 + vc * 16),
                 g_v + (size_t)(n0 + vr) * (NKV * DH) + (size_t)kvh * DH + vc * 8);
        }
    };

    // load Q tile (128 x 128) hi/lo
    #pragma unroll
    for (int i = 0; i < 8; i++) {
        int idx = tid + i * 256;
        int r = idx >> 4, ch = idx & 15;
        const size_t go = (size_t)(m0 + r) * (NH * DH) + (size_t)h * DH + ch * 8;
        *(uint4*)(sm + O_QH + r * 272 + ch * 16) = *(const uint4*)(g_qh + go);
        *(uint4*)(sm + O_QL + r * 272 + ch * 16) = *(const uint4*)(g_ql + go);
    }

    float oacc[16][4];
    #pragma unroll
    for (int j = 0; j < 16; j++)
        #pragma unroll
        for (int q = 0; q < 4; q++) oacc[j][q] = 0.f;
    float m_run0 = -1e30f, m_run1 = -1e30f, l_run0 = 0.f, l_run1 = 0.f;

    const int row0 = m0 + wm + gID;
    const int row1 = row0 + 8;
    const int warp_max_row = m0 + wm + 15;

    const int nblocks = (m0 >> 6) + 2;
    issue_kv(0, 0); CP_COMMIT();

    for (int blk = 0; blk < nblocks; blk++) {
        const int n0 = blk << 6;
        const bool more = (blk + 1 < nblocks);
        if (more) { issue_kv((blk + 1) << 6, (blk + 1) & 1); CP_COMMIT(); CP_WAIT(1); }
        else      { CP_WAIT(0); }
        __syncthreads();

        if (n0 <= warp_max_row) {
            const uint32_t kb = sb + O_KV0 + (uint32_t)(blk & 1) * KV_BUF;

            // ---- S = Q K^T (2 products) ----
            float sacc[8][4];
            #pragma unroll
            for (int j = 0; j < 8; j++)
                #pragma unroll
                for (int q = 0; q < 4; q++) sacc[j][q] = 0.f;

            #pragma unroll
            for (int ks = 0; ks < 8; ks++) {
                uint32_t aH[4], aL[4];
                uint32_t ro = sb + O_QH + (uint32_t)((wm + (lane & 15)) * 272
                                                     + ks * 32 + (lane >> 4) * 16);
                ldsm4(aH, ro);
                ldsm4(aL, ro + A2_Q);
                const uint32_t kro = kb
                    + (uint32_t)((ks * 16 + (lane & 15)) * 144 + (lane >> 4) * 16);
                #pragma unroll
                for (int nb = 0; nb < 4; nb++) {
                    uint32_t bk4[4];
                    ldsm4t(bk4, kro + (uint32_t)(nb * 32));
                    #pragma unroll
                    for (int hh = 0; hh < 2; hh++) {
                        float (&cc)[4] = sacc[nb * 2 + hh];
                        mma_f16(cc, aH, bk4[2 * hh], bk4[2 * hh + 1]);
                        mma_f16(cc, aL, bk4[2 * hh], bk4[2 * hh + 1]);
                    }
                }
            }

            // ---- online softmax ----
            float mx0 = -1e30f, mx1 = -1e30f;
            #pragma unroll
            for (int nb = 0; nb < 8; nb++) {
                #pragma unroll
                for (int j = 0; j < 2; j++) {
                    const int col = n0 + nb * 8 + tig * 2 + j;
                    float s0 = sacc[nb][j];
                    float s1 = sacc[nb][2 + j];
                    if (col > row0) s0 = -1e30f;
                    if (col > row1) s1 = -1e30f;
                    sacc[nb][j] = s0;
                    sacc[nb][2 + j] = s1;
                    mx0 = fmaxf(mx0, s0);
                    mx1 = fmaxf(mx1, s1);
                }
            }
            #pragma unroll
            for (int off = 1; off <= 2; off <<= 1) {
                mx0 = fmaxf(mx0, __shfl_xor_sync(0xffffffffu, mx0, off));
                mx1 = fmaxf(mx1, __shfl_xor_sync(0xffffffffu, mx1, off));
            }
            float mn0 = fmaxf(m_run0, mx0);
            float mn1 = fmaxf(m_run1, mx1);
            float cf0 = __expf(m_run0 - mn0);
            float cf1 = __expf(m_run1 - mn1);
            m_run0 = mn0; m_run1 = mn1;
            float su0 = 0.f, su1 = 0.f;
            #pragma unroll
            for (int nb = 0; nb < 8; nb++) {
                #pragma unroll
                for (int j = 0; j < 2; j++) {
                    float p0 = __expf(sacc[nb][j] - mn0);
                    float p1 = __expf(sacc[nb][2 + j] - mn1);
                    sacc[nb][j] = p0;
                    sacc[nb][2 + j] = p1;
                    su0 += p0;
                    su1 += p1;
                }
            }
            #pragma unroll
            for (int off = 1; off <= 2; off <<= 1) {
                su0 += __shfl_xor_sync(0xffffffffu, su0, off);
                su1 += __shfl_xor_sync(0xffffffffu, su1, off);
            }
            l_run0 = l_run0 * cf0 + su0;
            l_run1 = l_run1 * cf1 + su1;
            #pragma unroll
            for (int j = 0; j < 16; j++) {
                oacc[j][0] *= cf0;
                oacc[j][1] *= cf0;
                oacc[j][2] *= cf1;
                oacc[j][3] *= cf1;
            }

            // ---- O += P V (2 products; P split register-direct) ----
            #pragma unroll
            for (int ks = 0; ks < 4; ks++) {
                uint32_t ph[4], pl[4];
                split_pack_f16(sacc[2 * ks][0],     sacc[2 * ks][1],     ph[0], pl[0]);
                split_pack_f16(sacc[2 * ks][2],     sacc[2 * ks][3],     ph[1], pl[1]);
                split_pack_f16(sacc[2 * ks + 1][0], sacc[2 * ks + 1][1], ph[2], pl[2]);
                split_pack_f16(sacc[2 * ks + 1][2], sacc[2 * ks + 1][3], ph[3], pl[3]);
                const uint32_t vro = kb + A2_KT
                    + (uint32_t)((ks * 16 + (lane & 15)) * 272 + (lane >> 4) * 16);
                #pragma unroll
                for (int nbv = 0; nbv < 8; nbv++) {
                    uint32_t vb4[4];
                    ldsm4t(vb4, vro + (uint32_t)(nbv * 32));
                    #pragma unroll
                    for (int hh = 0; hh < 2; hh++) {
                        float (&cc)[4] = oacc[nbv * 2 + hh];
                        mma_f16(cc, ph, vb4[2 * hh], vb4[2 * hh + 1]);
                        mma_f16(cc, pl, vb4[2 * hh], vb4[2 * hh + 1]);
                    }
                }
            }
        }
        __syncthreads();
    }

    // epilogue: write fp16 hi/lo split of normalized output
    const float inv0 = 1.0f / l_run0;
    const float inv1 = 1.0f / l_run1;
    #pragma unroll
    for (int onb = 0; onb < 16; onb++) {
        const int col = h * DH + onb * 8 + tig * 2;
        const size_t i0 = (size_t)row0 * (NH * DH) + col;
        const size_t i1 = (size_t)row1 * (NH * DH) + col;
        uint32_t hh_, ll_;
        split_pack_f16(oacc[onb][0] * inv0, oacc[onb][1] * inv0, hh_, ll_);
        *(uint32_t*)(oh + i0) = hh_;
        *(uint32_t*)(ol + i0) = ll_;
        split_pack_f16(oacc[onb][2] * inv1, oacc[onb][3] * inv1, hh_, ll_);
        *(uint32_t*)(oh + i1) = hh_;
        *(uint32_t*)(ol + i1) = ll_;
    }
}

// ---------------------------------------------------------------------------
extern "C" void kernel_launch(void* const* d_in, const int* in_sizes, int n_in,
                              void* d_out, int out_size)
{
    const int*   positions = (const int*)d_in[0];
    const float* hs = (const float*)d_in[1];
    const float* Wq = (const float*)d_in[2];
    const float* bq = (const float*)d_in[3];
    const float* Wk = (const float*)d_in[4];
    const float* bk = (const float*)d_in[5];
    const float* Wv = (const float*)d_in[6];
    const float* bv = (const float*)d_in[7];
    const float* Wo = (const float*)d_in[8];

    float* out  = (float*)d_out;
    float* kout = out + (size_t)TSEQ * HID;
    float* vout = kout + (size_t)TSEQ * NKV * DH;

    float *qbuf;
    __half *hsh, *hsl, *qqh, *qql, *aah, *aal;
    cudaGetSymbolAddress((void**)&qbuf, g_q);
    cudaGetSymbolAddress((void**)&hsh, g_hsh);  cudaGetSymbolAddress((void**)&hsl, g_hsl);
    cudaGetSymbolAddress((void**)&qqh, g_qh);   cudaGetSymbolAddress((void**)&qql, g_ql);
    cudaGetSymbolAddress((void**)&aah, g_ah);   cudaGetSymbolAddress((void**)&aal, g_al);

    cudaFuncSetAttribute(tgemm_qkv, cudaFuncAttributeMaxDynamicSharedMemorySize, (int)TG_SMEM);
    cudaFuncSetAttribute(tgemm_o, cudaFuncAttributeMaxDynamicSharedMemorySize, (int)TG_SMEM);
    cudaFuncSetAttribute(attn_mma, cudaFuncAttributeMaxDynamicSharedMemorySize, (int)A2_SMEM);

    // 1. converts + rope table
    {
        int n4 = TSEQ * HID / 4;
        convert_split<<<n4 / 512, 256>>>((const float4*)hs, (uint2*)hsh, (uint2*)hsl, n4);
        convert_weights<<<(W_TOT8 + 255) / 256, 256>>>(
            (const float4*)Wq, (const float4*)Wk, (const float4*)Wv, (const float4*)Wo);
        rope_tab_kernel<<<(TSEQ * 64 + 255) / 256, 256>>>(positions);
    }

    // 2. fused QKV projection
    tgemm_qkv<<<dim3(48, 16), 256, TG_SMEM>>>(bq, bk, bv, qbuf, kout, vout);

    // 3. rope
    rope_q_kernel<<<(TSEQ * NH * 64 + 255) / 256, 256>>>(qbuf, qqh, qql);
    rope_k_kernel<<<(TSEQ * NKV * 64 + 255) / 256, 256>>>(kout);

    // 4. attention
    attn_mma<<<dim3(NH, TSEQ / 128), 256, A2_SMEM>>>(aah, aal);

    // 5. O projection
    tgemm_o<<<dim3(32, 16), 256, TG_SMEM>>>(out);
}